// round 12
// baseline (speedup 1.0000x reference)
#include <cuda_runtime.h>
#include <cuda_bf16.h>
#include <math.h>
#include <stdint.h>

#define B_ 4
#define T_ 1024
#define D_ 1024
#define H_ 16
#define HS_ 64
#define BT_ (B_*T_)
#define DECAY_C (-0.606531f)

// ---------------- scratch ----------------
__device__ float g_r  [BT_*D_];
__device__ float g_wl [BT_*D_];
__device__ float g_k  [BT_*D_];
__device__ float g_v  [BT_*D_];
__device__ float g_a  [BT_*D_];
__device__ float g_g  [BT_*D_];
__device__ float g_at [BT_*D_];
__device__ float g_bt [BT_*D_];
__device__ float g_hv [BT_*D_];
__device__ float g_rks[BT_*H_];
__device__ float g_y  [BT_*D_];
__device__ float g_ds [B_*H_*HS_*HS_];

// bf16 split operands
__device__ __align__(16) __nv_bfloat16 g_whiT[4][1024*1024];
__device__ __align__(16) __nv_bfloat16 g_wloT[4][1024*1024];
__device__ __align__(16) __nv_bfloat16 g_ahi[6][BT_*D_];
__device__ __align__(16) __nv_bfloat16 g_alo[6][BT_*D_];
__device__ __align__(16) __nv_bfloat16 g_zhi[BT_*D_];
__device__ __align__(16) __nv_bfloat16 g_zlo[BT_*D_];

// LoRA weight splits (zero-init; pads never written)
__device__ __align__(16) __nv_bfloat16 g_l1hi[(64+64+64+128)*1024];
__device__ __align__(16) __nv_bfloat16 g_l1lo[(64+64+64+128)*1024];
__device__ __align__(16) __nv_bfloat16 g_l2hi[1024*(64+64+64+128)];
__device__ __align__(16) __nv_bfloat16 g_l2lo[1024*(64+64+64+128)];
__device__ __align__(16) __nv_bfloat16 g_s1hi[BT_*(64+64+64+128)];
__device__ __align__(16) __nv_bfloat16 g_s1lo[BT_*(64+64+64+128)];

// ================= low-level helpers =================
__device__ __forceinline__ uint32_t smem_to_u32(const void* p) {
    uint32_t a;
    asm("{ .reg .u64 t; cvta.to.shared.u64 t, %1; cvt.u32.u64 %0, t; }" : "=r"(a) : "l"(p));
    return a;
}
__device__ __forceinline__ void cpasync16(uint32_t saddr, const void* g) {
    asm volatile("cp.async.cg.shared.global [%0], [%1], 16;" :: "r"(saddr), "l"(g));
}
#define CP_COMMIT() asm volatile("cp.async.commit_group;" ::: "memory")
#define CP_WAIT2()  asm volatile("cp.async.wait_group 2;" ::: "memory")
#define CP_WAIT1()  asm volatile("cp.async.wait_group 1;" ::: "memory")
#define CP_WAIT0()  asm volatile("cp.async.wait_group 0;" ::: "memory")

__device__ __forceinline__ void ldsm4(uint32_t* r, uint32_t addr) {
    asm volatile("ldmatrix.sync.aligned.m8n8.x4.shared.b16 {%0,%1,%2,%3}, [%4];"
                 : "=r"(r[0]), "=r"(r[1]), "=r"(r[2]), "=r"(r[3]) : "r"(addr));
}
__device__ __forceinline__ void mma16816(float* d, const uint32_t* a, const uint32_t* b) {
    asm volatile("mma.sync.aligned.m16n8k16.row.col.f32.bf16.bf16.f32 "
                 "{%0,%1,%2,%3}, {%4,%5,%6,%7}, {%8,%9}, {%0,%1,%2,%3};"
                 : "+f"(d[0]), "+f"(d[1]), "+f"(d[2]), "+f"(d[3])
                 : "r"(a[0]), "r"(a[1]), "r"(a[2]), "r"(a[3]), "r"(b[0]), "r"(b[1]));
}
__device__ __forceinline__ void split_bf(float x, __nv_bfloat16& h, __nv_bfloat16& l) {
    h = __float2bfloat16(x);
    l = __float2bfloat16(x - __bfloat162float(h));
}
__device__ __forceinline__ float actf(float v, int act) {
    if (act == 1) return tanhf(v);
    if (act == 2) return 1.f / (1.f + expf(-v));
    return v;
}

// dummy to keep ncu window on the big GEMM
__global__ void dummy_kernel() {}

// ================= transpose + split =================
struct TSJob { const float* W; int K, N; __nv_bfloat16 *hi, *lo; int stride; };
struct TSParams { TSJob j[12]; };

__global__ __launch_bounds__(256) void tsplit_kernel(TSParams P)
{
    TSJob J = P.j[blockIdx.z];
    int k0 = blockIdx.y*32, n0 = blockIdx.x*32;
    if (k0 >= J.K || n0 >= J.N) return;
    __shared__ float ts[32][33];
    int tx = threadIdx.x & 31, ty = threadIdx.x >> 5;
    #pragma unroll
    for (int i = 0; i < 4; i++)
        ts[ty+i*8][tx] = J.W[(size_t)(k0+ty+i*8)*J.N + n0+tx];
    __syncthreads();
    #pragma unroll
    for (int i = 0; i < 4; i++) {
        int r = ty + i*8;
        float v = ts[tx][r];
        __nv_bfloat16 h, l; split_bf(v, h, l);
        J.hi[(size_t)(n0+r)*J.stride + k0+tx] = h;
        J.lo[(size_t)(n0+r)*J.stride + k0+tx] = l;
    }
}

// ================= activation mix + split: read once, write all 6 =================
__global__ __launch_bounds__(256) void asplit_kernel(
    const float* __restrict__ cur, const float* __restrict__ prev,
    const float* __restrict__ lam)
{
    size_t e = ((size_t)blockIdx.x*256 + threadIdx.x)*4;
    float4 c = *(const float4*)(cur+e);
    float4 p = *(const float4*)(prev+e);
    float dx = p.x-c.x, dy = p.y-c.y, dz = p.z-c.z, dw = p.w-c.w;
    int col = (int)(e & 1023);
    #pragma unroll
    for (int z = 0; z < 6; z++) {
        float4 l4 = *(const float4*)(lam + z*D_ + col);
        float m0 = fmaf(l4.x, dx, c.x), m1 = fmaf(l4.y, dy, c.y);
        float m2 = fmaf(l4.z, dz, c.z), m3 = fmaf(l4.w, dw, c.w);
        __nv_bfloat16 h0,l0,h1,l1,h2,l2,h3,l3;
        split_bf(m0,h0,l0); split_bf(m1,h1,l1); split_bf(m2,h2,l2); split_bf(m3,h3,l3);
        __nv_bfloat162* hp = (__nv_bfloat162*)(g_ahi[z]+e);
        __nv_bfloat162* lp = (__nv_bfloat162*)(g_alo[z]+e);
        hp[0] = __nv_bfloat162(h0,h1); hp[1] = __nv_bfloat162(h2,h3);
        lp[0] = __nv_bfloat162(l0,l1); lp[1] = __nv_bfloat162(l2,l3);
    }
}

// ================= HMMA split-bf16 GEMM, BM=BN=128, 2-stage, 2 CTA/SM =============
struct MJob { const __nv_bfloat16 *ahi, *alo, *bhi, *blo; int lda, ldb, K;
              const float* bias; int act; float* c; };
struct MParams { MJob s[4]; };

#define MMA_STRIDE 40
#define TILE_ELE (128*MMA_STRIDE)
#define MMA_SMEM_BYTES (2*4*TILE_ELE*2)

__global__ __launch_bounds__(256,2) void mma_gemm(MParams P)
{
    extern __shared__ __align__(16) __nv_bfloat16 sm[];
    const uint32_t smb = smem_to_u32(sm);
    MJob S = P.s[blockIdx.z];
    const int tid = threadIdx.x, lane = tid & 31, w = tid >> 5;
    const int wm = w & 3, wn = w >> 2;
    const int brow = blockIdx.y * 128, bcol = blockIdx.x * 128;
    const int lda = S.lda, ldb = S.ldb;

    const __nv_bfloat16* gA0 = S.ahi + (size_t)brow*lda;
    const __nv_bfloat16* gA1 = S.alo + (size_t)brow*lda;
    const __nv_bfloat16* gB0 = S.bhi + (size_t)bcol*ldb;
    const __nv_bfloat16* gB1 = S.blo + (size_t)bcol*ldb;

    auto issue = [&](int c) {
        const int st = c & 1;
        const int r = tid >> 2, q = tid & 3;
        const int r2 = r + 64;
        const size_t ka = (size_t)c*32 + q*8;
        #pragma unroll
        for (int hl = 0; hl < 2; hl++) {
            const __nv_bfloat16* gA = hl ? gA1 : gA0;
            const __nv_bfloat16* gB = hl ? gB1 : gB0;
            uint32_t base = smb + 2u*((uint32_t)(st*4 + hl)*TILE_ELE);
            cpasync16(base + 2u*(r *MMA_STRIDE + q*8), gA + (size_t)r *lda + ka);
            cpasync16(base + 2u*(r2*MMA_STRIDE + q*8), gA + (size_t)r2*lda + ka);
            base = smb + 2u*((uint32_t)(st*4 + 2 + hl)*TILE_ELE);
            cpasync16(base + 2u*(r *MMA_STRIDE + q*8), gB + (size_t)r *ldb + ka);
            cpasync16(base + 2u*(r2*MMA_STRIDE + q*8), gB + (size_t)r2*ldb + ka);
        }
    };

    float acc[2][8][4];
    #pragma unroll
    for (int mi = 0; mi < 2; mi++)
        #pragma unroll
        for (int ni = 0; ni < 8; ni++)
            #pragma unroll
            for (int q = 0; q < 4; q++) acc[mi][ni][q] = 0.f;

    const int la15 = lane & 15;
    const int akc  = (lane >> 4) << 3;
    const int brow16 = ((lane >> 4) << 3) + (lane & 7);
    const int bkadd  = ((lane >> 3) & 1) << 3;

    const int nC = S.K >> 5;
    issue(0); CP_COMMIT();

    for (int c = 0; c < nC; c++) {
        if (c + 1 < nC) { issue(c + 1); CP_COMMIT(); CP_WAIT1(); }
        else            { CP_WAIT0(); }
        __syncthreads();

        const uint32_t stb = smb + 2u*(uint32_t)((c & 1)*4)*TILE_ELE;
        #pragma unroll
        for (int ks = 0; ks < 32; ks += 16) {
            uint32_t ah[2][4], al[2][4];
            #pragma unroll
            for (int mi = 0; mi < 2; mi++) {
                const int row = wm*32 + mi*16 + la15;
                const uint32_t ao = 2u*(row*MMA_STRIDE + ks + akc);
                ldsm4(ah[mi], stb + 0*2*TILE_ELE + ao);
                ldsm4(al[mi], stb + 1*2*TILE_ELE + ao);
            }
            #pragma unroll
            for (int ni2 = 0; ni2 < 4; ni2++) {
                const int nrow = wn*64 + ni2*16 + brow16;
                const uint32_t bo = 2u*(nrow*MMA_STRIDE + ks + bkadd);
                uint32_t bh4[4], bl4[4];
                ldsm4(bh4, stb + 2*2*TILE_ELE + bo);
                ldsm4(bl4, stb + 3*2*TILE_ELE + bo);
                #pragma unroll
                for (int half = 0; half < 2; half++) {
                    const int ni = ni2*2 + half;
                    #pragma unroll
                    for (int mi = 0; mi < 2; mi++) {
                        mma16816(acc[mi][ni], ah[mi], bh4 + half*2);
                        mma16816(acc[mi][ni], ah[mi], bl4 + half*2);
                        mma16816(acc[mi][ni], al[mi], bh4 + half*2);
                    }
                }
            }
        }
        __syncthreads();
    }

    const int g2 = lane >> 2, cc = lane & 3;
    #pragma unroll
    for (int mi = 0; mi < 2; mi++) {
        #pragma unroll
        for (int ni = 0; ni < 8; ni++) {
            const int row = brow + wm*32 + mi*16;
            const int col = bcol + wn*64 + ni*8 + 2*cc;
            float b0 = 0.f, b1 = 0.f;
            if (S.bias) { b0 = S.bias[col]; b1 = S.bias[col+1]; }
            float v0 = actf(acc[mi][ni][0] + b0, S.act);
            float v1 = actf(acc[mi][ni][1] + b1, S.act);
            float v2 = actf(acc[mi][ni][2] + b0, S.act);
            float v3 = actf(acc[mi][ni][3] + b1, S.act);
            *(float2*)(S.c + (size_t)(row + g2    )*1024 + col) = make_float2(v0, v1);
            *(float2*)(S.c + (size_t)(row + g2 + 8)*1024 + col) = make_float2(v2, v3);
        }
    }
}

// ================= HMMA split-bf16 GEMM, BM=64 BN=64 (LoRA stage-1), 2-stage ======
struct LJob { const __nv_bfloat16 *ahi, *alo, *bhi, *blo; int act;
              __nv_bfloat16 *ohi, *olo; int ostride, ocol; };
struct LParams { LJob s[5]; };

#define L_TILE (64*MMA_STRIDE)
#define L_STAGE (4*L_TILE)
#define L_SMEM_BYTES (2*L_STAGE*2)

__global__ __launch_bounds__(128,4) void mma_lora1(LParams P)
{
    extern __shared__ __align__(16) __nv_bfloat16 sm[];
    const uint32_t smb = smem_to_u32(sm);
    LJob S = P.s[blockIdx.z];
    const int tid = threadIdx.x, lane = tid & 31, w = tid >> 5;
    const int wm = w & 1, wn = w >> 1;
    const int brow = blockIdx.y * 64;

    const __nv_bfloat16* gA0 = S.ahi + (size_t)brow*1024;
    const __nv_bfloat16* gA1 = S.alo + (size_t)brow*1024;

    auto issue = [&](int c) {
        const int st = c & 1;
        const uint32_t sbase = smb + 2u*(uint32_t)(st*L_STAGE);
        const int r = tid >> 2, q = tid & 3, r2 = r + 32;
        const size_t ka = (size_t)c*32 + q*8;
        cpasync16(sbase + 2u*(r *MMA_STRIDE + q*8),              gA0   + (size_t)r *1024 + ka);
        cpasync16(sbase + 2u*(r2*MMA_STRIDE + q*8),              gA0   + (size_t)r2*1024 + ka);
        cpasync16(sbase + 2u*(L_TILE + r *MMA_STRIDE + q*8),     gA1   + (size_t)r *1024 + ka);
        cpasync16(sbase + 2u*(L_TILE + r2*MMA_STRIDE + q*8),     gA1   + (size_t)r2*1024 + ka);
        cpasync16(sbase + 2u*(2*L_TILE + r *MMA_STRIDE + q*8),   S.bhi + (size_t)r *1024 + ka);
        cpasync16(sbase + 2u*(2*L_TILE + r2*MMA_STRIDE + q*8),   S.bhi + (size_t)r2*1024 + ka);
        cpasync16(sbase + 2u*(3*L_TILE + r *MMA_STRIDE + q*8),   S.blo + (size_t)r *1024 + ka);
        cpasync16(sbase + 2u*(3*L_TILE + r2*MMA_STRIDE + q*8),   S.blo + (size_t)r2*1024 + ka);
    };

    float acc[2][4][4];
    #pragma unroll
    for (int mi = 0; mi < 2; mi++)
        #pragma unroll
        for (int ni = 0; ni < 4; ni++)
            #pragma unroll
            for (int q = 0; q < 4; q++) acc[mi][ni][q] = 0.f;

    const int la15 = lane & 15;
    const int akc  = (lane >> 4) << 3;
    const int brow16 = ((lane >> 4) << 3) + (lane & 7);
    const int bkadd  = ((lane >> 3) & 1) << 3;

    issue(0); CP_COMMIT();
    for (int c = 0; c < 32; c++) {
        if (c + 1 < 32) { issue(c + 1); CP_COMMIT(); CP_WAIT1(); }
        else            { CP_WAIT0(); }
        __syncthreads();

        const uint32_t stb = smb + 2u*(uint32_t)((c & 1)*L_STAGE);
        #pragma unroll
        for (int ks = 0; ks < 32; ks += 16) {
            uint32_t ah[2][4], al[2][4];
            #pragma unroll
            for (int mi = 0; mi < 2; mi++) {
                const int row = wm*32 + mi*16 + la15;
                const uint32_t ao = 2u*(row*MMA_STRIDE + ks + akc);
                ldsm4(ah[mi], stb + ao);
                ldsm4(al[mi], stb + 2u*L_TILE + ao);
            }
            #pragma unroll
            for (int ni2 = 0; ni2 < 2; ni2++) {
                const int nrow = wn*32 + ni2*16 + brow16;
                const uint32_t bo = 2u*(nrow*MMA_STRIDE + ks + bkadd);
                uint32_t bh4[4], bl4[4];
                ldsm4(bh4, stb + 2u*(2*L_TILE) + bo);
                ldsm4(bl4, stb + 2u*(3*L_TILE) + bo);
                #pragma unroll
                for (int half = 0; half < 2; half++) {
                    const int ni = ni2*2 + half;
                    #pragma unroll
                    for (int mi = 0; mi < 2; mi++) {
                        mma16816(acc[mi][ni], ah[mi], bh4 + half*2);
                        mma16816(acc[mi][ni], ah[mi], bl4 + half*2);
                        mma16816(acc[mi][ni], al[mi], bh4 + half*2);
                    }
                }
            }
        }
        __syncthreads();
    }

    const int g2 = lane >> 2, cc = lane & 3;
    #pragma unroll
    for (int mi = 0; mi < 2; mi++) {
        #pragma unroll
        for (int ni = 0; ni < 4; ni++) {
            const int row = brow + wm*32 + mi*16;
            const int col = S.ocol + wn*32 + ni*8 + 2*cc;
            #pragma unroll
            for (int half = 0; half < 2; half++) {
                float v0 = actf(acc[mi][ni][half*2+0], S.act);
                float v1 = actf(acc[mi][ni][half*2+1], S.act);
                __nv_bfloat16 h0,l0,h1,l1;
                split_bf(v0,h0,l0); split_bf(v1,h1,l1);
                size_t o = (size_t)(row + g2 + half*8)*S.ostride + col;
                *(__nv_bfloat162*)(S.ohi + o) = __nv_bfloat162(h0,h1);
                *(__nv_bfloat162*)(S.olo + o) = __nv_bfloat162(l0,l1);
            }
        }
    }
}

// ---------------- post ----------------
__launch_bounds__(512)
__global__ void post_kernel(float* __restrict__ K_, float* __restrict__ V_,
    float* __restrict__ WL, const float* __restrict__ A_, const float* __restrict__ R_,
    const float* __restrict__ HV, const float* __restrict__ vfirst,
    const float* __restrict__ kkv, const float* __restrict__ kav, const float* __restrict__ rkv,
    float* __restrict__ AT, float* __restrict__ BTt, float* __restrict__ RKS)
{
    int bt = blockIdx.x;
    int h = threadIdx.x >> 5, lane = threadIdx.x & 31;
    int base = bt * D_ + h * HS_;
    int ce0 = h*HS_ + lane, ce1 = ce0 + 32;
    int i0 = base + lane, i1 = i0 + 32;

    float k0 = K_[i0], k1 = K_[i1];
    float kk0 = k0 * kkv[ce0], kk1 = k1 * kkv[ce1];
    float n2 = kk0*kk0 + kk1*kk1;
    #pragma unroll
    for (int o = 16; o; o >>= 1) n2 += __shfl_xor_sync(0xffffffffu, n2, o);
    float inv = rsqrtf(n2);
    kk0 *= inv; kk1 *= inv;

    float a0 = A_[i0], a1 = A_[i1];
    AT[i0] = -kk0;      AT[i1] = -kk1;
    BTt[i0] = kk0 * a0; BTt[i1] = kk1 * a1;

    k0 *= 1.f + (a0 - 1.f) * kav[ce0];
    k1 *= 1.f + (a1 - 1.f) * kav[ce1];
    K_[i0] = k0; K_[i1] = k1;

    float v0 = V_[i0], v1 = V_[i1];
    float hg0 = HV[i0], hg1 = HV[i1];
    v0 += (vfirst[i0] - v0) * hg0;
    v1 += (vfirst[i1] - v1) * hg1;
    V_[i0] = v0; V_[i1] = v1;

    float w0 = WL[i0], w1 = WL[i1];
    WL[i0] = expf(DECAY_C / (1.f + expf(-w0)));
    WL[i1] = expf(DECAY_C / (1.f + expf(-w1)));

    float rs = R_[i0]*k0*rkv[ce0] + R_[i1]*k1*rkv[ce1];
    #pragma unroll
    for (int o = 16; o; o >>= 1) rs += __shfl_xor_sync(0xffffffffu, rs, o);
    if (lane == 0) RKS[bt*H_ + h] = rs;
}

// ---------------- scan: cp.async ring, loads balanced across ALL 8 warps ----------
#define LOAD8(dst, ptr) do { \
    float4 u0 = *(const float4*)(ptr); float4 u1 = *(const float4*)((ptr)+4); \
    dst[0]=u0.x; dst[1]=u0.y; dst[2]=u0.z; dst[3]=u0.w; \
    dst[4]=u1.x; dst[5]=u1.y; dst[6]=u1.z; dst[7]=u1.w; } while(0)

__launch_bounds__(256)
__global__ void scan_kernel(const float* __restrict__ R_, const float* __restrict__ W_,
    const float* __restrict__ K_, const float* __restrict__ V_,
    const float* __restrict__ AT, const float* __restrict__ BTt,
    float* __restrict__ Y, float* __restrict__ S)
{
    __shared__ __align__(16) float4 vbuf[4][88];
    __shared__ float redA[2][8][32];
    __shared__ float redY[2][8][32];
    int bid = blockIdx.x;
    int b = bid >> 5; int rem = bid & 31; int h = rem >> 1; int half = rem & 1;
    int tid = threadIdx.x;
    int kg = tid >> 5, vl = tid & 31;
    int kb = kg * 8;

    // balanced loader mapping: load l (0..87) -> warp (l&7), lane (l>>3)
    // so thread (warp=kg, lane=vl) with vl<11 owns l = vl*8 + kg.
    const bool loader = (vl < 11);
    int l = vl*8 + kg;               // < 88 guaranteed when vl<11
    const float* msrc = nullptr;
    if (loader) {
        const float* bp; int inner;
        if (l < 80) {
            int arr = l / 16, q = l % 16;
            bp = (arr==0) ? AT : (arr==1) ? W_ : (arr==2) ? BTt : (arr==3) ? K_ : R_;
            inner = q * 4;
        } else {
            bp = V_; inner = half*32 + (l - 80) * 4;
        }
        msrc = bp + h*HS_ + inner;
    }

    const uint32_t vbase = smem_to_u32(vbuf);
    const uint32_t vslot = (uint32_t)l * 16u;

    float s[8];
    #pragma unroll
    for (int i = 0; i < 8; i++) s[i] = 0.f;
    float yprev = 0.f;

    size_t row0 = (size_t)b * T_ * D_;
    const size_t yofs = row0 + h*HS_ + half*32 + vl;

    #pragma unroll
    for (int i = 0; i < 3; i++) {
        if (loader) cpasync16(vbase + (uint32_t)i*(88*16) + vslot, msrc + row0 + (size_t)i*D_);
        CP_COMMIT();
    }
    CP_WAIT2();
    __syncthreads();

    for (int t = 0; t < T_; t++) {
        const int cb = t & 1;
        if (loader && t + 3 < T_)
            cpasync16(vbase + (uint32_t)((t+3)&3)*(88*16) + vslot, msrc + row0 + (size_t)(t+3)*D_);
        CP_COMMIT();
        CP_WAIT2();

        const float* base = (const float*)vbuf[t & 3];
        float atr[8], wr[8], btr[8], kr[8], rr[8];
        LOAD8(atr, base       + kb); LOAD8(wr, base +  64 + kb); LOAD8(btr, base + 128 + kb);
        LOAD8(kr,  base + 192 + kb); LOAD8(rr, base + 256 + kb);
        float vt = base[320 + vl];

        float p0 = s[0]*atr[0] + s[1]*atr[1], p1 = s[2]*atr[2] + s[3]*atr[3];
        float p2 = s[4]*atr[4] + s[5]*atr[5], p3 = s[6]*atr[6] + s[7]*atr[7];
        redA[cb][kg][vl] = (p0 + p1) + (p2 + p3);
        redY[cb][kg][vl] = yprev;
        __syncthreads();

        float sa = 0.f;
        #pragma unroll
        for (int g2 = 0; g2 < 8; g2++) sa += redA[cb][g2][vl];

        if (kg == 0 && t > 0) {
            float yy = 0.f;
            #pragma unroll
            for (int g2 = 0; g2 < 8; g2++) yy += redY[cb][g2][vl];
            Y[yofs + (size_t)(t-1)*D_] = yy;
        }

        float y = 0.f;
        #pragma unroll
        for (int i = 0; i < 8; i++) {
            float sn = s[i]*wr[i] + sa*btr[i] + vt*kr[i];
            s[i] = sn;
            y += sn * rr[i];
        }
        yprev = y;
    }
    redY[0][kg][vl] = yprev;
    __syncthreads();
    if (kg == 0) {
        float yy = 0.f;
        #pragma unroll
        for (int g2 = 0; g2 < 8; g2++) yy += redY[0][g2][vl];
        Y[yofs + (size_t)(T_-1)*D_] = yy;
    }

    int v = half*32 + vl;
    size_t sb2 = ((size_t)(b*H_ + h)*HS_ + v)*HS_ + kb;
    *(float4*)(S + sb2)     = make_float4(s[0], s[1], s[2], s[3]);
    *(float4*)(S + sb2 + 4) = make_float4(s[4], s[5], s[6], s[7]);
}

// ---------------- groupnorm + residual + gate + bf16 split ----------------
__launch_bounds__(512)
__global__ void gn_kernel(const float* __restrict__ Y, const float* __restrict__ V_,
    const float* __restrict__ G_, const float* __restrict__ RKS,
    const float* __restrict__ gsc, const float* __restrict__ gbi)
{
    int bt = blockIdx.x;
    int h = threadIdx.x >> 5, lane = threadIdx.x & 31;
    int base = bt * D_ + h * HS_;
    int i0 = base + lane, i1 = i0 + 32;
    int ce0 = h*HS_ + lane, ce1 = ce0 + 32;
    float y0 = Y[i0], y1 = Y[i1];
    float sm = y0 + y1, sq = y0*y0 + y1*y1;
    #pragma unroll
    for (int o = 16; o; o >>= 1) {
        sm += __shfl_xor_sync(0xffffffffu, sm, o);
        sq += __shfl_xor_sync(0xffffffffu, sq, o);
    }
    float mu  = sm * (1.f/64.f);
    float var = sq * (1.f/64.f) - mu*mu;
    float inv = rsqrtf(var + 1e-5f);
    float rk  = RKS[bt*H_ + h];
    float o0 = ((y0 - mu)*inv*gsc[ce0] + gbi[ce0] + rk*V_[i0]) * G_[i0];
    float o1 = ((y1 - mu)*inv*gsc[ce1] + gbi[ce1] + rk*V_[i1]) * G_[i1];
    __nv_bfloat16 h0,l0,h1,l1;
    split_bf(o0, h0, l0); split_bf(o1, h1, l1);
    g_zhi[i0] = h0; g_zhi[i1] = h1;
    g_zlo[i0] = l0; g_zlo[i1] = l1;
}

// ---------------- launch ----------------
extern "C" void kernel_launch(void* const* d_in, const int* in_sizes, int n_in,
                              void* d_out, int out_size)
{
    const float* cur    = (const float*)d_in[0];
    const float* prev   = (const float*)d_in[1];
    const float* vfirst = (const float*)d_in[2];
    const float* lam    = (const float*)d_in[3];
    const float* rw_W   = (const float*)d_in[4];
    const float* w1     = (const float*)d_in[5];
    const float* w2     = (const float*)d_in[6];
    const float* w2b    = (const float*)d_in[7];
    const float* kw     = (const float*)d_in[8];
    const float* vw     = (const float*)d_in[9];
    const float* a1     = (const float*)d_in[10];
    const float* a2     = (const float*)d_in[11];
    const float* a2b    = (const float*)d_in[12];
    const float* v1     = (const float*)d_in[13];
    const float* v2     = (const float*)d_in[14];
    const float* v2b    = (const float*)d_in[15];
    const float* g1     = (const float*)d_in[16];
    const float* g2     = (const float*)d_in[17];
    const float* g2b    = (const float*)d_in[18];
    const float* k_k    = (const float*)d_in[19];
    const float* k_a    = (const float*)d_in[20];
    const float* r_k    = (const float*)d_in[21];
    const float* gsc    = (const float*)d_in[22];
    const float* gbi    = (const float*)d_in[23];
    const float* outW   = (const float*)d_in[24];
    (void)in_sizes; (void)n_in;

    float *pr,*pwl,*pk,*pv,*pa,*pg,*pat,*pbt,*phv,*prks,*py,*pds;
    cudaGetSymbolAddress((void**)&pr,  g_r);
    cudaGetSymbolAddress((void**)&pwl, g_wl);
    cudaGetSymbolAddress((void**)&pk,  g_k);
    cudaGetSymbolAddress((void**)&pv,  g_v);
    cudaGetSymbolAddress((void**)&pa,  g_a);
    cudaGetSymbolAddress((void**)&pg,  g_g);
    cudaGetSymbolAddress((void**)&pat, g_at);
    cudaGetSymbolAddress((void**)&pbt, g_bt);
    cudaGetSymbolAddress((void**)&phv, g_hv);
    cudaGetSymbolAddress((void**)&prks,g_rks);
    cudaGetSymbolAddress((void**)&py,  g_y);
    cudaGetSymbolAddress((void**)&pds, g_ds);

    __nv_bfloat16 *pwhiT,*pwloT,*pahi,*palo,*pzhi,*pzlo,*pl1h,*pl1l,*pl2h,*pl2l,*ps1h,*ps1l;
    cudaGetSymbolAddress((void**)&pwhiT, g_whiT);
    cudaGetSymbolAddress((void**)&pwloT, g_wloT);
    cudaGetSymbolAddress((void**)&pahi,  g_ahi);
    cudaGetSymbolAddress((void**)&palo,  g_alo);
    cudaGetSymbolAddress((void**)&pzhi,  g_zhi);
    cudaGetSymbolAddress((void**)&pzlo,  g_zlo);
    cudaGetSymbolAddress((void**)&pl1h,  g_l1hi);
    cudaGetSymbolAddress((void**)&pl1l,  g_l1lo);
    cudaGetSymbolAddress((void**)&pl2h,  g_l2hi);
    cudaGetSymbolAddress((void**)&pl2l,  g_l2lo);
    cudaGetSymbolAddress((void**)&ps1h,  g_s1hi);
    cudaGetSymbolAddress((void**)&ps1l,  g_s1lo);

    float* out = (float*)d_out;
    const int YN = BT_*D_;
    const int SN = B_*H_*HS_*HS_;
    float* stateOut = (out_size >= YN + SN) ? (out + YN) : pds;

    cudaFuncSetAttribute(mma_gemm,  cudaFuncAttributeMaxDynamicSharedMemorySize, MMA_SMEM_BYTES);
    cudaFuncSetAttribute(mma_lora1, cudaFuncAttributeMaxDynamicSharedMemorySize, L_SMEM_BYTES);

    const size_t O_W1 = 0, O_A1 = 64*1024, O_V1 = 128*1024, O_G1 = 192*1024;
    const size_t P_W2 = 0, P_A2 = 1024*64, P_V2 = 2*1024*64, P_G2 = 3*1024*64;
    const size_t S_HW = 0, S_HA = (size_t)BT_*64, S_HV = (size_t)BT_*128, S_HG = (size_t)BT_*192;

    dummy_kernel<<<1, 32>>>();

    TSParams TP;
    TP.j[0]  = { rw_W, 1024, 1024, pwhiT + 0*1024*1024, pwloT + 0*1024*1024, 1024 };
    TP.j[1]  = { kw,   1024, 1024, pwhiT + 1*1024*1024, pwloT + 1*1024*1024, 1024 };
    TP.j[2]  = { vw,   1024, 1024, pwhiT + 2*1024*1024, pwloT + 2*1024*1024, 1024 };
    TP.j[3]  = { outW, 1024, 1024, pwhiT + 3*1024*1024, pwloT + 3*1024*1024, 1024 };
    TP.j[4]  = { w1, 1024,  64, pl1h + O_W1, pl1l + O_W1, 1024 };
    TP.j[5]  = { a1, 1024,  64, pl1h + O_A1, pl1l + O_A1, 1024 };
    TP.j[6]  = { v1, 1024,  32, pl1h + O_V1, pl1l + O_V1, 1024 };
    TP.j[7]  = { g1, 1024, 128, pl1h + O_G1, pl1l + O_G1, 1024 };
    TP.j[8]  = { w2,  64, 1024, pl2h + P_W2, pl2l + P_W2,  64 };
    TP.j[9]  = { a2,  64, 1024, pl2h + P_A2, pl2l + P_A2,  64 };
    TP.j[10] = { v2,  32, 1024, pl2h + P_V2, pl2l + P_V2,  64 };
    TP.j[11] = { g2, 128, 1024, pl2h + P_G2, pl2l + P_G2, 128 };
    tsplit_kernel<<<dim3(32,32,12), 256>>>(TP);
    asplit_kernel<<<4096, 256>>>(cur, prev, lam);

    MParams Prkv;
    {
        const int br[3] = {0, 2, 3};
        float* cs[3] = {pr, pk, pv};
        for (int z = 0; z < 3; z++) {
            Prkv.s[z] = { pahi + (size_t)br[z]*BT_*D_, palo + (size_t)br[z]*BT_*D_,
                          pwhiT + (size_t)z*1024*1024, pwloT + (size_t)z*1024*1024,
                          1024, 1024, 1024, nullptr, 0, cs[z] };
        }
        Prkv.s[3] = Prkv.s[0];
    }
    mma_gemm<<<dim3(8,32,3), 256, MMA_SMEM_BYTES>>>(Prkv);

    LParams LP;
    LP.s[0] = { pahi + (size_t)1*BT_*D_, palo + (size_t)1*BT_*D_, pl1h+O_W1, pl1l+O_W1, 1, ps1h+S_HW, ps1l+S_HW,  64, 0 };
    LP.s[1] = { pahi + (size_t)4*BT_*D_, palo + (size_t)4*BT_*D_, pl1h+O_A1, pl1l+O_A1, 0, ps1h+S_HA, ps1l+S_HA,  64, 0 };
    LP.s[2] = { pahi + (size_t)3*BT_*D_, palo + (size_t)3*BT_*D_, pl1h+O_V1, pl1l+O_V1, 0, ps1h+S_HV, ps1l+S_HV,  64, 0 };
    LP.s[3] = { pahi + (size_t)5*BT_*D_, palo + (size_t)5*BT_*D_, pl1h+O_G1,         pl1l+O_G1,         2, ps1h+S_HG, ps1l+S_HG, 128, 0 };
    LP.s[4] = { pahi + (size_t)5*BT_*D_, palo + (size_t)5*BT_*D_, pl1h+O_G1+64*1024, pl1l+O_G1+64*1024, 2, ps1h+S_HG, ps1l+S_HG, 128, 64 };
    mma_lora1<<<dim3(1,64,5), 128, L_SMEM_BYTES>>>(LP);

    MParams P2;
    P2.s[0] = { ps1h+S_HW, ps1l+S_HW, pl2h+P_W2, pl2l+P_W2,  64,  64,  64, w2b, 0, pwl };
    P2.s[1] = { ps1h+S_HA, ps1l+S_HA, pl2h+P_A2, pl2l+P_A2,  64,  64,  64, a2b, 2, pa  };
    P2.s[2] = { ps1h+S_HV, ps1l+S_HV, pl2h+P_V2, pl2l+P_V2,  64,  64,  64, v2b, 2, phv };
    P2.s[3] = { ps1h+S_HG, ps1l+S_HG, pl2h+P_G2, pl2l+P_G2, 128, 128, 128, g2b, 0, pg  };
    mma_gemm<<<dim3(8,32,4), 256, MMA_SMEM_BYTES>>>(P2);

    post_kernel<<<BT_, 512>>>(pk, pv, pwl, pa, pr, phv, vfirst, k_k, k_a, r_k, pat, pbt, prks);
    scan_kernel<<<128, 256>>>(pr, pwl, pk, pv, pat, pbt, py, stateOut);
    gn_kernel  <<<BT_, 512>>>(py, pv, pg, prks, gsc, gbi);

    MParams Pout;
    Pout.s[0] = { pzhi, pzlo, pwhiT + (size_t)3*1024*1024, pwloT + (size_t)3*1024*1024,
                  1024, 1024, 1024, nullptr, 0, out };
    Pout.s[1] = Pout.s[0]; Pout.s[2] = Pout.s[0]; Pout.s[3] = Pout.s[0];
    mma_gemm<<<dim3(8,32,1), 256, MMA_SMEM_BYTES>>>(Pout);

    if (out_size >= YN + SN + YN)
        cudaMemcpyAsync(out + YN + SN, vfirst, (size_t)YN*sizeof(float),
                        cudaMemcpyDeviceToDevice, 0);
}

// round 15
// speedup vs baseline: 1.0496x; 1.0496x over previous
#include <cuda_runtime.h>
#include <cuda_bf16.h>
#include <math.h>
#include <stdint.h>

#define B_ 4
#define T_ 1024
#define D_ 1024
#define H_ 16
#define HS_ 64
#define BT_ (B_*T_)
#define DECAY_C (-0.606531f)

// ---------------- scratch ----------------
__device__ float g_r  [BT_*D_];
__device__ float g_wl [BT_*D_];
__device__ float g_k  [BT_*D_];
__device__ float g_v  [BT_*D_];
__device__ float g_a  [BT_*D_];
__device__ float g_g  [BT_*D_];
__device__ float g_at [BT_*D_];
__device__ float g_bt [BT_*D_];
__device__ float g_hv [BT_*D_];
__device__ float g_rks[BT_*H_];
__device__ float g_y  [BT_*D_];
__device__ float g_ds [B_*H_*HS_*HS_];

// bf16 split operands
__device__ __align__(16) __nv_bfloat16 g_whiT[4][1024*1024];
__device__ __align__(16) __nv_bfloat16 g_wloT[4][1024*1024];
__device__ __align__(16) __nv_bfloat16 g_ahi[6][BT_*D_];
__device__ __align__(16) __nv_bfloat16 g_alo[6][BT_*D_];
__device__ __align__(16) __nv_bfloat16 g_zhi[BT_*D_];
__device__ __align__(16) __nv_bfloat16 g_zlo[BT_*D_];

// LoRA weight splits (zero-init; pads never written)
__device__ __align__(16) __nv_bfloat16 g_l1hi[(64+64+64+128)*1024];
__device__ __align__(16) __nv_bfloat16 g_l1lo[(64+64+64+128)*1024];
__device__ __align__(16) __nv_bfloat16 g_l2hi[1024*(64+64+64+128)];
__device__ __align__(16) __nv_bfloat16 g_l2lo[1024*(64+64+64+128)];
__device__ __align__(16) __nv_bfloat16 g_s1hi[BT_*(64+64+64+128)];
__device__ __align__(16) __nv_bfloat16 g_s1lo[BT_*(64+64+64+128)];

// ================= low-level helpers =================
__device__ __forceinline__ uint32_t smem_to_u32(const void* p) {
    uint32_t a;
    asm("{ .reg .u64 t; cvta.to.shared.u64 t, %1; cvt.u32.u64 %0, t; }" : "=r"(a) : "l"(p));
    return a;
}
__device__ __forceinline__ void cpasync16(uint32_t saddr, const void* g) {
    asm volatile("cp.async.cg.shared.global [%0], [%1], 16;" :: "r"(saddr), "l"(g));
}
#define CP_COMMIT() asm volatile("cp.async.commit_group;" ::: "memory")
#define CP_WAIT6()  asm volatile("cp.async.wait_group 6;" ::: "memory")
#define CP_WAIT1()  asm volatile("cp.async.wait_group 1;" ::: "memory")
#define CP_WAIT0()  asm volatile("cp.async.wait_group 0;" ::: "memory")

__device__ __forceinline__ void ldsm4(uint32_t* r, uint32_t addr) {
    asm volatile("ldmatrix.sync.aligned.m8n8.x4.shared.b16 {%0,%1,%2,%3}, [%4];"
                 : "=r"(r[0]), "=r"(r[1]), "=r"(r[2]), "=r"(r[3]) : "r"(addr));
}
__device__ __forceinline__ void mma16816(float* d, const uint32_t* a, const uint32_t* b) {
    asm volatile("mma.sync.aligned.m16n8k16.row.col.f32.bf16.bf16.f32 "
                 "{%0,%1,%2,%3}, {%4,%5,%6,%7}, {%8,%9}, {%0,%1,%2,%3};"
                 : "+f"(d[0]), "+f"(d[1]), "+f"(d[2]), "+f"(d[3])
                 : "r"(a[0]), "r"(a[1]), "r"(a[2]), "r"(a[3]), "r"(b[0]), "r"(b[1]));
}
__device__ __forceinline__ void split_bf(float x, __nv_bfloat16& h, __nv_bfloat16& l) {
    h = __float2bfloat16(x);
    l = __float2bfloat16(x - __bfloat162float(h));
}
__device__ __forceinline__ float actf(float v, int act) {
    if (act == 1) return tanhf(v);
    if (act == 2) return 1.f / (1.f + expf(-v));
    return v;
}

// dummy to keep ncu window on the big GEMM
__global__ void dummy_kernel() {}

// ================= transpose + split =================
struct TSJob { const float* W; int K, N; __nv_bfloat16 *hi, *lo; int stride; };
struct TSParams { TSJob j[12]; };

__global__ __launch_bounds__(256) void tsplit_kernel(TSParams P)
{
    TSJob J = P.j[blockIdx.z];
    int k0 = blockIdx.y*32, n0 = blockIdx.x*32;
    if (k0 >= J.K || n0 >= J.N) return;
    __shared__ float ts[32][33];
    int tx = threadIdx.x & 31, ty = threadIdx.x >> 5;
    #pragma unroll
    for (int i = 0; i < 4; i++)
        ts[ty+i*8][tx] = J.W[(size_t)(k0+ty+i*8)*J.N + n0+tx];
    __syncthreads();
    #pragma unroll
    for (int i = 0; i < 4; i++) {
        int r = ty + i*8;
        float v = ts[tx][r];
        __nv_bfloat16 h, l; split_bf(v, h, l);
        J.hi[(size_t)(n0+r)*J.stride + k0+tx] = h;
        J.lo[(size_t)(n0+r)*J.stride + k0+tx] = l;
    }
}

// ================= activation mix + split: read once, write all 6 =================
__global__ __launch_bounds__(256) void asplit_kernel(
    const float* __restrict__ cur, const float* __restrict__ prev,
    const float* __restrict__ lam)
{
    size_t e = ((size_t)blockIdx.x*256 + threadIdx.x)*4;
    float4 c = *(const float4*)(cur+e);
    float4 p = *(const float4*)(prev+e);
    float dx = p.x-c.x, dy = p.y-c.y, dz = p.z-c.z, dw = p.w-c.w;
    int col = (int)(e & 1023);
    #pragma unroll
    for (int z = 0; z < 6; z++) {
        float4 l4 = *(const float4*)(lam + z*D_ + col);
        float m0 = fmaf(l4.x, dx, c.x), m1 = fmaf(l4.y, dy, c.y);
        float m2 = fmaf(l4.z, dz, c.z), m3 = fmaf(l4.w, dw, c.w);
        __nv_bfloat16 h0,l0,h1,l1,h2,l2,h3,l3;
        split_bf(m0,h0,l0); split_bf(m1,h1,l1); split_bf(m2,h2,l2); split_bf(m3,h3,l3);
        __nv_bfloat162* hp = (__nv_bfloat162*)(g_ahi[z]+e);
        __nv_bfloat162* lp = (__nv_bfloat162*)(g_alo[z]+e);
        hp[0] = __nv_bfloat162(h0,h1); hp[1] = __nv_bfloat162(h2,h3);
        lp[0] = __nv_bfloat162(l0,l1); lp[1] = __nv_bfloat162(l2,l3);
    }
}

// ================= HMMA split-bf16 GEMM, BM=BN=128, 2-stage, 2 CTA/SM =============
struct MJob { const __nv_bfloat16 *ahi, *alo, *bhi, *blo; int lda, ldb, K;
              const float* bias; int act; float* c; };
struct MParams { MJob s[4]; };

#define MMA_STRIDE 40
#define TILE_ELE (128*MMA_STRIDE)
#define MMA_SMEM_BYTES (2*4*TILE_ELE*2)

__global__ __launch_bounds__(256,2) void mma_gemm(MParams P)
{
    extern __shared__ __align__(16) __nv_bfloat16 sm[];
    const uint32_t smb = smem_to_u32(sm);
    MJob S = P.s[blockIdx.z];
    const int tid = threadIdx.x, lane = tid & 31, w = tid >> 5;
    const int wm = w & 3, wn = w >> 2;
    const int brow = blockIdx.y * 128, bcol = blockIdx.x * 128;
    const int lda = S.lda, ldb = S.ldb;

    const __nv_bfloat16* gA0 = S.ahi + (size_t)brow*lda;
    const __nv_bfloat16* gA1 = S.alo + (size_t)brow*lda;
    const __nv_bfloat16* gB0 = S.bhi + (size_t)bcol*ldb;
    const __nv_bfloat16* gB1 = S.blo + (size_t)bcol*ldb;

    auto issue = [&](int c) {
        const int st = c & 1;
        const int r = tid >> 2, q = tid & 3;
        const int r2 = r + 64;
        const size_t ka = (size_t)c*32 + q*8;
        #pragma unroll
        for (int hl = 0; hl < 2; hl++) {
            const __nv_bfloat16* gA = hl ? gA1 : gA0;
            const __nv_bfloat16* gB = hl ? gB1 : gB0;
            uint32_t base = smb + 2u*((uint32_t)(st*4 + hl)*TILE_ELE);
            cpasync16(base + 2u*(r *MMA_STRIDE + q*8), gA + (size_t)r *lda + ka);
            cpasync16(base + 2u*(r2*MMA_STRIDE + q*8), gA + (size_t)r2*lda + ka);
            base = smb + 2u*((uint32_t)(st*4 + 2 + hl)*TILE_ELE);
            cpasync16(base + 2u*(r *MMA_STRIDE + q*8), gB + (size_t)r *ldb + ka);
            cpasync16(base + 2u*(r2*MMA_STRIDE + q*8), gB + (size_t)r2*ldb + ka);
        }
    };

    float acc[2][8][4];
    #pragma unroll
    for (int mi = 0; mi < 2; mi++)
        #pragma unroll
        for (int ni = 0; ni < 8; ni++)
            #pragma unroll
            for (int q = 0; q < 4; q++) acc[mi][ni][q] = 0.f;

    const int la15 = lane & 15;
    const int akc  = (lane >> 4) << 3;
    const int brow16 = ((lane >> 4) << 3) + (lane & 7);
    const int bkadd  = ((lane >> 3) & 1) << 3;

    const int nC = S.K >> 5;
    issue(0); CP_COMMIT();

    for (int c = 0; c < nC; c++) {
        if (c + 1 < nC) { issue(c + 1); CP_COMMIT(); CP_WAIT1(); }
        else            { CP_WAIT0(); }
        __syncthreads();

        const uint32_t stb = smb + 2u*(uint32_t)((c & 1)*4)*TILE_ELE;
        #pragma unroll
        for (int ks = 0; ks < 32; ks += 16) {
            uint32_t ah[2][4], al[2][4];
            #pragma unroll
            for (int mi = 0; mi < 2; mi++) {
                const int row = wm*32 + mi*16 + la15;
                const uint32_t ao = 2u*(row*MMA_STRIDE + ks + akc);
                ldsm4(ah[mi], stb + 0*2*TILE_ELE + ao);
                ldsm4(al[mi], stb + 1*2*TILE_ELE + ao);
            }
            #pragma unroll
            for (int ni2 = 0; ni2 < 4; ni2++) {
                const int nrow = wn*64 + ni2*16 + brow16;
                const uint32_t bo = 2u*(nrow*MMA_STRIDE + ks + bkadd);
                uint32_t bh4[4], bl4[4];
                ldsm4(bh4, stb + 2*2*TILE_ELE + bo);
                ldsm4(bl4, stb + 3*2*TILE_ELE + bo);
                #pragma unroll
                for (int half = 0; half < 2; half++) {
                    const int ni = ni2*2 + half;
                    #pragma unroll
                    for (int mi = 0; mi < 2; mi++) {
                        mma16816(acc[mi][ni], ah[mi], bh4 + half*2);
                        mma16816(acc[mi][ni], ah[mi], bl4 + half*2);
                        mma16816(acc[mi][ni], al[mi], bh4 + half*2);
                    }
                }
            }
        }
        __syncthreads();
    }

    const int g2 = lane >> 2, cc = lane & 3;
    #pragma unroll
    for (int mi = 0; mi < 2; mi++) {
        #pragma unroll
        for (int ni = 0; ni < 8; ni++) {
            const int row = brow + wm*32 + mi*16;
            const int col = bcol + wn*64 + ni*8 + 2*cc;
            float b0 = 0.f, b1 = 0.f;
            if (S.bias) { b0 = S.bias[col]; b1 = S.bias[col+1]; }
            float v0 = actf(acc[mi][ni][0] + b0, S.act);
            float v1 = actf(acc[mi][ni][1] + b1, S.act);
            float v2 = actf(acc[mi][ni][2] + b0, S.act);
            float v3 = actf(acc[mi][ni][3] + b1, S.act);
            *(float2*)(S.c + (size_t)(row + g2    )*1024 + col) = make_float2(v0, v1);
            *(float2*)(S.c + (size_t)(row + g2 + 8)*1024 + col) = make_float2(v2, v3);
        }
    }
}

// ================= HMMA split-bf16 GEMM, BM=64 BN=64 (LoRA stage-1), 2-stage ======
struct LJob { const __nv_bfloat16 *ahi, *alo, *bhi, *blo; int act;
              __nv_bfloat16 *ohi, *olo; int ostride, ocol; };
struct LParams { LJob s[5]; };

#define L_TILE (64*MMA_STRIDE)
#define L_STAGE (4*L_TILE)
#define L_SMEM_BYTES (2*L_STAGE*2)

__global__ __launch_bounds__(128,4) void mma_lora1(LParams P)
{
    extern __shared__ __align__(16) __nv_bfloat16 sm[];
    const uint32_t smb = smem_to_u32(sm);
    LJob S = P.s[blockIdx.z];
    const int tid = threadIdx.x, lane = tid & 31, w = tid >> 5;
    const int wm = w & 1, wn = w >> 1;
    const int brow = blockIdx.y * 64;

    const __nv_bfloat16* gA0 = S.ahi + (size_t)brow*1024;
    const __nv_bfloat16* gA1 = S.alo + (size_t)brow*1024;

    auto issue = [&](int c) {
        const int st = c & 1;
        const uint32_t sbase = smb + 2u*(uint32_t)(st*L_STAGE);
        const int r = tid >> 2, q = tid & 3, r2 = r + 32;
        const size_t ka = (size_t)c*32 + q*8;
        cpasync16(sbase + 2u*(r *MMA_STRIDE + q*8),              gA0   + (size_t)r *1024 + ka);
        cpasync16(sbase + 2u*(r2*MMA_STRIDE + q*8),              gA0   + (size_t)r2*1024 + ka);
        cpasync16(sbase + 2u*(L_TILE + r *MMA_STRIDE + q*8),     gA1   + (size_t)r *1024 + ka);
        cpasync16(sbase + 2u*(L_TILE + r2*MMA_STRIDE + q*8),     gA1   + (size_t)r2*1024 + ka);
        cpasync16(sbase + 2u*(2*L_TILE + r *MMA_STRIDE + q*8),   S.bhi + (size_t)r *1024 + ka);
        cpasync16(sbase + 2u*(2*L_TILE + r2*MMA_STRIDE + q*8),   S.bhi + (size_t)r2*1024 + ka);
        cpasync16(sbase + 2u*(3*L_TILE + r *MMA_STRIDE + q*8),   S.blo + (size_t)r *1024 + ka);
        cpasync16(sbase + 2u*(3*L_TILE + r2*MMA_STRIDE + q*8),   S.blo + (size_t)r2*1024 + ka);
    };

    float acc[2][4][4];
    #pragma unroll
    for (int mi = 0; mi < 2; mi++)
        #pragma unroll
        for (int ni = 0; ni < 4; ni++)
            #pragma unroll
            for (int q = 0; q < 4; q++) acc[mi][ni][q] = 0.f;

    const int la15 = lane & 15;
    const int akc  = (lane >> 4) << 3;
    const int brow16 = ((lane >> 4) << 3) + (lane & 7);
    const int bkadd  = ((lane >> 3) & 1) << 3;

    issue(0); CP_COMMIT();
    for (int c = 0; c < 32; c++) {
        if (c + 1 < 32) { issue(c + 1); CP_COMMIT(); CP_WAIT1(); }
        else            { CP_WAIT0(); }
        __syncthreads();

        const uint32_t stb = smb + 2u*(uint32_t)((c & 1)*L_STAGE);
        #pragma unroll
        for (int ks = 0; ks < 32; ks += 16) {
            uint32_t ah[2][4], al[2][4];
            #pragma unroll
            for (int mi = 0; mi < 2; mi++) {
                const int row = wm*32 + mi*16 + la15;
                const uint32_t ao = 2u*(row*MMA_STRIDE + ks + akc);
                ldsm4(ah[mi], stb + ao);
                ldsm4(al[mi], stb + 2u*L_TILE + ao);
            }
            #pragma unroll
            for (int ni2 = 0; ni2 < 2; ni2++) {
                const int nrow = wn*32 + ni2*16 + brow16;
                const uint32_t bo = 2u*(nrow*MMA_STRIDE + ks + bkadd);
                uint32_t bh4[4], bl4[4];
                ldsm4(bh4, stb + 2u*(2*L_TILE) + bo);
                ldsm4(bl4, stb + 2u*(3*L_TILE) + bo);
                #pragma unroll
                for (int half = 0; half < 2; half++) {
                    const int ni = ni2*2 + half;
                    #pragma unroll
                    for (int mi = 0; mi < 2; mi++) {
                        mma16816(acc[mi][ni], ah[mi], bh4 + half*2);
                        mma16816(acc[mi][ni], ah[mi], bl4 + half*2);
                        mma16816(acc[mi][ni], al[mi], bh4 + half*2);
                    }
                }
            }
        }
        __syncthreads();
    }

    const int g2 = lane >> 2, cc = lane & 3;
    #pragma unroll
    for (int mi = 0; mi < 2; mi++) {
        #pragma unroll
        for (int ni = 0; ni < 4; ni++) {
            const int row = brow + wm*32 + mi*16;
            const int col = S.ocol + wn*32 + ni*8 + 2*cc;
            #pragma unroll
            for (int half = 0; half < 2; half++) {
                float v0 = actf(acc[mi][ni][half*2+0], S.act);
                float v1 = actf(acc[mi][ni][half*2+1], S.act);
                __nv_bfloat16 h0,l0,h1,l1;
                split_bf(v0,h0,l0); split_bf(v1,h1,l1);
                size_t o = (size_t)(row + g2 + half*8)*S.ostride + col;
                *(__nv_bfloat162*)(S.ohi + o) = __nv_bfloat162(h0,h1);
                *(__nv_bfloat162*)(S.olo + o) = __nv_bfloat162(l0,l1);
            }
        }
    }
}

// ---------------- post ----------------
__launch_bounds__(512)
__global__ void post_kernel(float* __restrict__ K_, float* __restrict__ V_,
    float* __restrict__ WL, const float* __restrict__ A_, const float* __restrict__ R_,
    const float* __restrict__ HV, const float* __restrict__ vfirst,
    const float* __restrict__ kkv, const float* __restrict__ kav, const float* __restrict__ rkv,
    float* __restrict__ AT, float* __restrict__ BTt, float* __restrict__ RKS)
{
    int bt = blockIdx.x;
    int h = threadIdx.x >> 5, lane = threadIdx.x & 31;
    int base = bt * D_ + h * HS_;
    int ce0 = h*HS_ + lane, ce1 = ce0 + 32;
    int i0 = base + lane, i1 = i0 + 32;

    float k0 = K_[i0], k1 = K_[i1];
    float kk0 = k0 * kkv[ce0], kk1 = k1 * kkv[ce1];
    float n2 = kk0*kk0 + kk1*kk1;
    #pragma unroll
    for (int o = 16; o; o >>= 1) n2 += __shfl_xor_sync(0xffffffffu, n2, o);
    float inv = rsqrtf(n2);
    kk0 *= inv; kk1 *= inv;

    float a0 = A_[i0], a1 = A_[i1];
    AT[i0] = -kk0;      AT[i1] = -kk1;
    BTt[i0] = kk0 * a0; BTt[i1] = kk1 * a1;

    k0 *= 1.f + (a0 - 1.f) * kav[ce0];
    k1 *= 1.f + (a1 - 1.f) * kav[ce1];
    K_[i0] = k0; K_[i1] = k1;

    float v0 = V_[i0], v1 = V_[i1];
    float hg0 = HV[i0], hg1 = HV[i1];
    v0 += (vfirst[i0] - v0) * hg0;
    v1 += (vfirst[i1] - v1) * hg1;
    V_[i0] = v0; V_[i1] = v1;

    float w0 = WL[i0], w1 = WL[i1];
    WL[i0] = expf(DECAY_C / (1.f + expf(-w0)));
    WL[i1] = expf(DECAY_C / (1.f + expf(-w1)));

    float rs = R_[i0]*k0*rkv[ce0] + R_[i1]*k1*rkv[ce1];
    #pragma unroll
    for (int o = 16; o; o >>= 1) rs += __shfl_xor_sync(0xffffffffu, rs, o);
    if (lane == 0) RKS[bt*H_ + h] = rs;
}

// ---------------- scan: cp.async 8-slot ring (6 steps of slack), 1 barrier/step ---
#define LOAD8(dst, ptr) do { \
    float4 u0 = *(const float4*)(ptr); float4 u1 = *(const float4*)((ptr)+4); \
    dst[0]=u0.x; dst[1]=u0.y; dst[2]=u0.z; dst[3]=u0.w; \
    dst[4]=u1.x; dst[5]=u1.y; dst[6]=u1.z; dst[7]=u1.w; } while(0)

__launch_bounds__(256)
__global__ void scan_kernel(const float* __restrict__ R_, const float* __restrict__ W_,
    const float* __restrict__ K_, const float* __restrict__ V_,
    const float* __restrict__ AT, const float* __restrict__ BTt,
    float* __restrict__ Y, float* __restrict__ S)
{
    __shared__ __align__(16) float4 vbuf[8][88];
    __shared__ float redA[2][8][32];
    __shared__ float redY[2][8][32];
    int bid = blockIdx.x;
    int b = bid >> 5; int rem = bid & 31; int h = rem >> 1; int half = rem & 1;
    int tid = threadIdx.x;
    int kg = tid >> 5, vl = tid & 31;
    int kb = kg * 8;

    const float* msrc = nullptr;
    if (tid < 88) {
        const float* bp; int inner;
        if (tid < 80) {
            int arr = tid / 16, q = tid % 16;
            bp = (arr==0) ? AT : (arr==1) ? W_ : (arr==2) ? BTt : (arr==3) ? K_ : R_;
            inner = q * 4;
        } else {
            bp = V_; inner = half*32 + (tid - 80) * 4;
        }
        msrc = bp + h*HS_ + inner;
    }

    const uint32_t vbase = smem_to_u32(vbuf);
    const uint32_t vslot = (uint32_t)tid * 16u;

    float s[8];
    #pragma unroll
    for (int i = 0; i < 8; i++) s[i] = 0.f;
    float yprev = 0.f;

    size_t row0 = (size_t)b * T_ * D_;
    const size_t yofs = row0 + h*HS_ + half*32 + vl;

    // preamble: prefetch t = 0..6 into slots 0..6
    #pragma unroll
    for (int i = 0; i < 7; i++) {
        if (tid < 88) cpasync16(vbase + (uint32_t)i*(88*16) + vslot, msrc + row0 + (size_t)i*D_);
        CP_COMMIT();
    }
    CP_WAIT6();           // slot 0 complete
    __syncthreads();

    for (int t = 0; t < T_; t++) {
        const int cb = t & 1;
        // prefetch t+7; commit always (group ids aligned); wait leaves slot t+1 landed
        if (tid < 88 && t + 7 < T_)
            cpasync16(vbase + (uint32_t)((t+7)&7)*(88*16) + vslot, msrc + row0 + (size_t)(t+7)*D_);
        CP_COMMIT();
        CP_WAIT6();

        const float* base = (const float*)vbuf[t & 7];
        float atr[8], wr[8], btr[8], kr[8], rr[8];
        LOAD8(atr, base       + kb); LOAD8(wr, base +  64 + kb); LOAD8(btr, base + 128 + kb);
        LOAD8(kr,  base + 192 + kb); LOAD8(rr, base + 256 + kb);
        float vt = base[320 + vl];

        float p0 = s[0]*atr[0] + s[1]*atr[1], p1 = s[2]*atr[2] + s[3]*atr[3];
        float p2 = s[4]*atr[4] + s[5]*atr[5], p3 = s[6]*atr[6] + s[7]*atr[7];
        redA[cb][kg][vl] = (p0 + p1) + (p2 + p3);
        redY[cb][kg][vl] = yprev;
        __syncthreads();

        float sa = 0.f;
        #pragma unroll
        for (int g2 = 0; g2 < 8; g2++) sa += redA[cb][g2][vl];

        if (kg == 0 && t > 0) {
            float yy = 0.f;
            #pragma unroll
            for (int g2 = 0; g2 < 8; g2++) yy += redY[cb][g2][vl];
            Y[yofs + (size_t)(t-1)*D_] = yy;
        }

        float y = 0.f;
        #pragma unroll
        for (int i = 0; i < 8; i++) {
            float sn = s[i]*wr[i] + sa*btr[i] + vt*kr[i];
            s[i] = sn;
            y += sn * rr[i];
        }
        yprev = y;
    }
    redY[0][kg][vl] = yprev;
    __syncthreads();
    if (kg == 0) {
        float yy = 0.f;
        #pragma unroll
        for (int g2 = 0; g2 < 8; g2++) yy += redY[0][g2][vl];
        Y[yofs + (size_t)(T_-1)*D_] = yy;
    }

    int v = half*32 + vl;
    size_t sb2 = ((size_t)(b*H_ + h)*HS_ + v)*HS_ + kb;
    *(float4*)(S + sb2)     = make_float4(s[0], s[1], s[2], s[3]);
    *(float4*)(S + sb2 + 4) = make_float4(s[4], s[5], s[6], s[7]);
}

// ---------------- groupnorm + residual + gate + bf16 split ----------------
__launch_bounds__(512)
__global__ void gn_kernel(const float* __restrict__ Y, const float* __restrict__ V_,
    const float* __restrict__ G_, const float* __restrict__ RKS,
    const float* __restrict__ gsc, const float* __restrict__ gbi)
{
    int bt = blockIdx.x;
    int h = threadIdx.x >> 5, lane = threadIdx.x & 31;
    int base = bt * D_ + h * HS_;
    int i0 = base + lane, i1 = i0 + 32;
    int ce0 = h*HS_ + lane, ce1 = ce0 + 32;
    float y0 = Y[i0], y1 = Y[i1];
    float sm = y0 + y1, sq = y0*y0 + y1*y1;
    #pragma unroll
    for (int o = 16; o; o >>= 1) {
        sm += __shfl_xor_sync(0xffffffffu, sm, o);
        sq += __shfl_xor_sync(0xffffffffu, sq, o);
    }
    float mu  = sm * (1.f/64.f);
    float var = sq * (1.f/64.f) - mu*mu;
    float inv = rsqrtf(var + 1e-5f);
    float rk  = RKS[bt*H_ + h];
    float o0 = ((y0 - mu)*inv*gsc[ce0] + gbi[ce0] + rk*V_[i0]) * G_[i0];
    float o1 = ((y1 - mu)*inv*gsc[ce1] + gbi[ce1] + rk*V_[i1]) * G_[i1];
    __nv_bfloat16 h0,l0,h1,l1;
    split_bf(o0, h0, l0); split_bf(o1, h1, l1);
    g_zhi[i0] = h0; g_zhi[i1] = h1;
    g_zlo[i0] = l0; g_zlo[i1] = l1;
}

// ---------------- launch ----------------
extern "C" void kernel_launch(void* const* d_in, const int* in_sizes, int n_in,
                              void* d_out, int out_size)
{
    const float* cur    = (const float*)d_in[0];
    const float* prev   = (const float*)d_in[1];
    const float* vfirst = (const float*)d_in[2];
    const float* lam    = (const float*)d_in[3];
    const float* rw_W   = (const float*)d_in[4];
    const float* w1     = (const float*)d_in[5];
    const float* w2     = (const float*)d_in[6];
    const float* w2b    = (const float*)d_in[7];
    const float* kw     = (const float*)d_in[8];
    const float* vw     = (const float*)d_in[9];
    const float* a1     = (const float*)d_in[10];
    const float* a2     = (const float*)d_in[11];
    const float* a2b    = (const float*)d_in[12];
    const float* v1     = (const float*)d_in[13];
    const float* v2     = (const float*)d_in[14];
    const float* v2b    = (const float*)d_in[15];
    const float* g1     = (const float*)d_in[16];
    const float* g2     = (const float*)d_in[17];
    const float* g2b    = (const float*)d_in[18];
    const float* k_k    = (const float*)d_in[19];
    const float* k_a    = (const float*)d_in[20];
    const float* r_k    = (const float*)d_in[21];
    const float* gsc    = (const float*)d_in[22];
    const float* gbi    = (const float*)d_in[23];
    const float* outW   = (const float*)d_in[24];
    (void)in_sizes; (void)n_in;

    float *pr,*pwl,*pk,*pv,*pa,*pg,*pat,*pbt,*phv,*prks,*py,*pds;
    cudaGetSymbolAddress((void**)&pr,  g_r);
    cudaGetSymbolAddress((void**)&pwl, g_wl);
    cudaGetSymbolAddress((void**)&pk,  g_k);
    cudaGetSymbolAddress((void**)&pv,  g_v);
    cudaGetSymbolAddress((void**)&pa,  g_a);
    cudaGetSymbolAddress((void**)&pg,  g_g);
    cudaGetSymbolAddress((void**)&pat, g_at);
    cudaGetSymbolAddress((void**)&pbt, g_bt);
    cudaGetSymbolAddress((void**)&phv, g_hv);
    cudaGetSymbolAddress((void**)&prks,g_rks);
    cudaGetSymbolAddress((void**)&py,  g_y);
    cudaGetSymbolAddress((void**)&pds, g_ds);

    __nv_bfloat16 *pwhiT,*pwloT,*pahi,*palo,*pzhi,*pzlo,*pl1h,*pl1l,*pl2h,*pl2l,*ps1h,*ps1l;
    cudaGetSymbolAddress((void**)&pwhiT, g_whiT);
    cudaGetSymbolAddress((void**)&pwloT, g_wloT);
    cudaGetSymbolAddress((void**)&pahi,  g_ahi);
    cudaGetSymbolAddress((void**)&palo,  g_alo);
    cudaGetSymbolAddress((void**)&pzhi,  g_zhi);
    cudaGetSymbolAddress((void**)&pzlo,  g_zlo);
    cudaGetSymbolAddress((void**)&pl1h,  g_l1hi);
    cudaGetSymbolAddress((void**)&pl1l,  g_l1lo);
    cudaGetSymbolAddress((void**)&pl2h,  g_l2hi);
    cudaGetSymbolAddress((void**)&pl2l,  g_l2lo);
    cudaGetSymbolAddress((void**)&ps1h,  g_s1hi);
    cudaGetSymbolAddress((void**)&ps1l,  g_s1lo);

    float* out = (float*)d_out;
    const int YN = BT_*D_;
    const int SN = B_*H_*HS_*HS_;
    float* stateOut = (out_size >= YN + SN) ? (out + YN) : pds;

    cudaFuncSetAttribute(mma_gemm,  cudaFuncAttributeMaxDynamicSharedMemorySize, MMA_SMEM_BYTES);
    cudaFuncSetAttribute(mma_lora1, cudaFuncAttributeMaxDynamicSharedMemorySize, L_SMEM_BYTES);

    const size_t O_W1 = 0, O_A1 = 64*1024, O_V1 = 128*1024, O_G1 = 192*1024;
    const size_t P_W2 = 0, P_A2 = 1024*64, P_V2 = 2*1024*64, P_G2 = 3*1024*64;
    const size_t S_HW = 0, S_HA = (size_t)BT_*64, S_HV = (size_t)BT_*128, S_HG = (size_t)BT_*192;

    dummy_kernel<<<1, 32>>>();

    TSParams TP;
    TP.j[0]  = { rw_W, 1024, 1024, pwhiT + 0*1024*1024, pwloT + 0*1024*1024, 1024 };
    TP.j[1]  = { kw,   1024, 1024, pwhiT + 1*1024*1024, pwloT + 1*1024*1024, 1024 };
    TP.j[2]  = { vw,   1024, 1024, pwhiT + 2*1024*1024, pwloT + 2*1024*1024, 1024 };
    TP.j[3]  = { outW, 1024, 1024, pwhiT + 3*1024*1024, pwloT + 3*1024*1024, 1024 };
    TP.j[4]  = { w1, 1024,  64, pl1h + O_W1, pl1l + O_W1, 1024 };
    TP.j[5]  = { a1, 1024,  64, pl1h + O_A1, pl1l + O_A1, 1024 };
    TP.j[6]  = { v1, 1024,  32, pl1h + O_V1, pl1l + O_V1, 1024 };
    TP.j[7]  = { g1, 1024, 128, pl1h + O_G1, pl1l + O_G1, 1024 };
    TP.j[8]  = { w2,  64, 1024, pl2h + P_W2, pl2l + P_W2,  64 };
    TP.j[9]  = { a2,  64, 1024, pl2h + P_A2, pl2l + P_A2,  64 };
    TP.j[10] = { v2,  32, 1024, pl2h + P_V2, pl2l + P_V2,  64 };
    TP.j[11] = { g2, 128, 1024, pl2h + P_G2, pl2l + P_G2, 128 };
    tsplit_kernel<<<dim3(32,32,12), 256>>>(TP);
    asplit_kernel<<<4096, 256>>>(cur, prev, lam);

    MParams Prkv;
    {
        const int br[3] = {0, 2, 3};
        float* cs[3] = {pr, pk, pv};
        for (int z = 0; z < 3; z++) {
            Prkv.s[z] = { pahi + (size_t)br[z]*BT_*D_, palo + (size_t)br[z]*BT_*D_,
                          pwhiT + (size_t)z*1024*1024, pwloT + (size_t)z*1024*1024,
                          1024, 1024, 1024, nullptr, 0, cs[z] };
        }
        Prkv.s[3] = Prkv.s[0];
    }
    mma_gemm<<<dim3(8,32,3), 256, MMA_SMEM_BYTES>>>(Prkv);

    LParams LP;
    LP.s[0] = { pahi + (size_t)1*BT_*D_, palo + (size_t)1*BT_*D_, pl1h+O_W1, pl1l+O_W1, 1, ps1h+S_HW, ps1l+S_HW,  64, 0 };
    LP.s[1] = { pahi + (size_t)4*BT_*D_, palo + (size_t)4*BT_*D_, pl1h+O_A1, pl1l+O_A1, 0, ps1h+S_HA, ps1l+S_HA,  64, 0 };
    LP.s[2] = { pahi + (size_t)3*BT_*D_, palo + (size_t)3*BT_*D_, pl1h+O_V1, pl1l+O_V1, 0, ps1h+S_HV, ps1l+S_HV,  64, 0 };
    LP.s[3] = { pahi + (size_t)5*BT_*D_, palo + (size_t)5*BT_*D_, pl1h+O_G1,         pl1l+O_G1,         2, ps1h+S_HG, ps1l+S_HG, 128, 0 };
    LP.s[4] = { pahi + (size_t)5*BT_*D_, palo + (size_t)5*BT_*D_, pl1h+O_G1+64*1024, pl1l+O_G1+64*1024, 2, ps1h+S_HG, ps1l+S_HG, 128, 64 };
    mma_lora1<<<dim3(1,64,5), 128, L_SMEM_BYTES>>>(LP);

    MParams P2;
    P2.s[0] = { ps1h+S_HW, ps1l+S_HW, pl2h+P_W2, pl2l+P_W2,  64,  64,  64, w2b, 0, pwl };
    P2.s[1] = { ps1h+S_HA, ps1l+S_HA, pl2h+P_A2, pl2l+P_A2,  64,  64,  64, a2b, 2, pa  };
    P2.s[2] = { ps1h+S_HV, ps1l+S_HV, pl2h+P_V2, pl2l+P_V2,  64,  64,  64, v2b, 2, phv };
    P2.s[3] = { ps1h+S_HG, ps1l+S_HG, pl2h+P_G2, pl2l+P_G2, 128, 128, 128, g2b, 0, pg  };
    mma_gemm<<<dim3(8,32,4), 256, MMA_SMEM_BYTES>>>(P2);

    post_kernel<<<BT_, 512>>>(pk, pv, pwl, pa, pr, phv, vfirst, k_k, k_a, r_k, pat, pbt, prks);
    scan_kernel<<<128, 256>>>(pr, pwl, pk, pv, pat, pbt, py, stateOut);
    gn_kernel  <<<BT_, 512>>>(py, pv, pg, prks, gsc, gbi);

    MParams Pout;
    Pout.s[0] = { pzhi, pzlo, pwhiT + (size_t)3*1024*1024, pwloT + (size_t)3*1024*1024,
                  1024, 1024, 1024, nullptr, 0, out };
    Pout.s[1] = Pout.s[0]; Pout.s[2] = Pout.s[0]; Pout.s[3] = Pout.s[0];
    mma_gemm<<<dim3(8,32,1), 256, MMA_SMEM_BYTES>>>(Pout);

    if (out_size >= YN + SN + YN)
        cudaMemcpyAsync(out + YN + SN, vfirst, (size_t)YN*sizeof(float),
                        cudaMemcpyDeviceToDevice, 0);
}

// round 17
// speedup vs baseline: 1.1269x; 1.0736x over previous
#include <cuda_runtime.h>
#include <cuda_bf16.h>
#include <math.h>
#include <stdint.h>

#define B_ 4
#define T_ 1024
#define D_ 1024
#define H_ 16
#define HS_ 64
#define BT_ (B_*T_)
#define DECAY_C (-0.606531f)

// ---------------- scratch ----------------
__device__ float g_r  [BT_*D_];
__device__ float g_wl [BT_*D_];
__device__ float g_k  [BT_*D_];
__device__ float g_v  [BT_*D_];
__device__ float g_a  [BT_*D_];
__device__ float g_g  [BT_*D_];
__device__ float g_at [BT_*D_];
__device__ float g_bt [BT_*D_];
__device__ float g_hv [BT_*D_];
__device__ float g_rks[BT_*H_];
__device__ float g_y  [BT_*D_];
__device__ float g_ds [B_*H_*HS_*HS_];

// bf16 split operands
__device__ __align__(16) __nv_bfloat16 g_whiT[4][1024*1024];
__device__ __align__(16) __nv_bfloat16 g_wloT[4][1024*1024];
__device__ __align__(16) __nv_bfloat16 g_ahi[6][BT_*D_];
__device__ __align__(16) __nv_bfloat16 g_alo[6][BT_*D_];
__device__ __align__(16) __nv_bfloat16 g_zhi[BT_*D_];
__device__ __align__(16) __nv_bfloat16 g_zlo[BT_*D_];

// LoRA weight splits (zero-init; pads never written)
__device__ __align__(16) __nv_bfloat16 g_l1hi[(64+64+64+128)*1024];
__device__ __align__(16) __nv_bfloat16 g_l1lo[(64+64+64+128)*1024];
__device__ __align__(16) __nv_bfloat16 g_l2hi[1024*(64+64+64+128)];
__device__ __align__(16) __nv_bfloat16 g_l2lo[1024*(64+64+64+128)];
__device__ __align__(16) __nv_bfloat16 g_s1hi[BT_*(64+64+64+128)];
__device__ __align__(16) __nv_bfloat16 g_s1lo[BT_*(64+64+64+128)];

// ================= low-level helpers =================
__device__ __forceinline__ uint32_t smem_to_u32(const void* p) {
    uint32_t a;
    asm("{ .reg .u64 t; cvta.to.shared.u64 t, %1; cvt.u32.u64 %0, t; }" : "=r"(a) : "l"(p));
    return a;
}
__device__ __forceinline__ void cpasync16(uint32_t saddr, const void* g) {
    asm volatile("cp.async.cg.shared.global [%0], [%1], 16;" :: "r"(saddr), "l"(g));
}
#define CP_COMMIT() asm volatile("cp.async.commit_group;" ::: "memory")
#define CP_WAIT6()  asm volatile("cp.async.wait_group 6;" ::: "memory")
#define CP_WAIT1()  asm volatile("cp.async.wait_group 1;" ::: "memory")
#define CP_WAIT0()  asm volatile("cp.async.wait_group 0;" ::: "memory")

__device__ __forceinline__ void ldsm4(uint32_t* r, uint32_t addr) {
    asm volatile("ldmatrix.sync.aligned.m8n8.x4.shared.b16 {%0,%1,%2,%3}, [%4];"
                 : "=r"(r[0]), "=r"(r[1]), "=r"(r[2]), "=r"(r[3]) : "r"(addr));
}
__device__ __forceinline__ void mma16816(float* d, const uint32_t* a, const uint32_t* b) {
    asm volatile("mma.sync.aligned.m16n8k16.row.col.f32.bf16.bf16.f32 "
                 "{%0,%1,%2,%3}, {%4,%5,%6,%7}, {%8,%9}, {%0,%1,%2,%3};"
                 : "+f"(d[0]), "+f"(d[1]), "+f"(d[2]), "+f"(d[3])
                 : "r"(a[0]), "r"(a[1]), "r"(a[2]), "r"(a[3]), "r"(b[0]), "r"(b[1]));
}
__device__ __forceinline__ void split_bf(float x, __nv_bfloat16& h, __nv_bfloat16& l) {
    h = __float2bfloat16(x);
    l = __float2bfloat16(x - __bfloat162float(h));
}
__device__ __forceinline__ float actf(float v, int act) {
    if (act == 1) return tanhf(v);
    if (act == 2) return 1.f / (1.f + expf(-v));
    return v;
}

// swizzled byte offset within an unpadded 128x32-elem (64B-row) tile:
// row r, 16B chunk q -> physical chunk q ^ ((r>>1)&3)
#define SWZ(r, q) ((uint32_t)((r)*64u + ((uint32_t)(((q) ^ (((r)>>1)&3))) << 4)))

// dummy to keep ncu window on the big GEMM
__global__ void dummy_kernel() {}

// ================= transpose + split =================
struct TSJob { const float* W; int K, N; __nv_bfloat16 *hi, *lo; int stride; };
struct TSParams { TSJob j[12]; };

__global__ __launch_bounds__(256) void tsplit_kernel(TSParams P)
{
    TSJob J = P.j[blockIdx.z];
    int k0 = blockIdx.y*32, n0 = blockIdx.x*32;
    if (k0 >= J.K || n0 >= J.N) return;
    __shared__ float ts[32][33];
    int tx = threadIdx.x & 31, ty = threadIdx.x >> 5;
    #pragma unroll
    for (int i = 0; i < 4; i++)
        ts[ty+i*8][tx] = J.W[(size_t)(k0+ty+i*8)*J.N + n0+tx];
    __syncthreads();
    #pragma unroll
    for (int i = 0; i < 4; i++) {
        int r = ty + i*8;
        float v = ts[tx][r];
        __nv_bfloat16 h, l; split_bf(v, h, l);
        J.hi[(size_t)(n0+r)*J.stride + k0+tx] = h;
        J.lo[(size_t)(n0+r)*J.stride + k0+tx] = l;
    }
}

// ================= activation mix + split: read once, write all 6 =================
__global__ __launch_bounds__(256) void asplit_kernel(
    const float* __restrict__ cur, const float* __restrict__ prev,
    const float* __restrict__ lam)
{
    size_t e = ((size_t)blockIdx.x*256 + threadIdx.x)*4;
    float4 c = *(const float4*)(cur+e);
    float4 p = *(const float4*)(prev+e);
    float dx = p.x-c.x, dy = p.y-c.y, dz = p.z-c.z, dw = p.w-c.w;
    int col = (int)(e & 1023);
    #pragma unroll
    for (int z = 0; z < 6; z++) {
        float4 l4 = *(const float4*)(lam + z*D_ + col);
        float m0 = fmaf(l4.x, dx, c.x), m1 = fmaf(l4.y, dy, c.y);
        float m2 = fmaf(l4.z, dz, c.z), m3 = fmaf(l4.w, dw, c.w);
        __nv_bfloat16 h0,l0,h1,l1,h2,l2,h3,l3;
        split_bf(m0,h0,l0); split_bf(m1,h1,l1); split_bf(m2,h2,l2); split_bf(m3,h3,l3);
        __nv_bfloat162* hp = (__nv_bfloat162*)(g_ahi[z]+e);
        __nv_bfloat162* lp = (__nv_bfloat162*)(g_alo[z]+e);
        hp[0] = __nv_bfloat162(h0,h1); hp[1] = __nv_bfloat162(h2,h3);
        lp[0] = __nv_bfloat162(l0,l1); lp[1] = __nv_bfloat162(l2,l3);
    }
}

// ==== HMMA split-bf16 GEMM, BM=BN=128, 3-stage swizzled, 1 barrier/chunk, 2 CTA/SM
struct MJob { const __nv_bfloat16 *ahi, *alo, *bhi, *blo; int lda, ldb, K;
              const float* bias; int act; float* c; };
struct MParams { MJob s[4]; };

#define TILE_BYTES 8192u                 // 128 rows x 64 B (32 bf16), unpadded
#define STAGE_BYTES (4u*TILE_BYTES)      // Ahi|Alo|Bhi|Blo
#define MMA_SMEM_BYTES (3*4*8192)        // 3 stages = 96 KB

__global__ __launch_bounds__(256,2) void mma_gemm(MParams P)
{
    extern __shared__ __align__(16) __nv_bfloat16 sm[];
    const uint32_t smb = smem_to_u32(sm);
    MJob S = P.s[blockIdx.z];
    const int tid = threadIdx.x, lane = tid & 31, w = tid >> 5;
    const int wm = w & 3, wn = w >> 2;
    const int brow = blockIdx.y * 128, bcol = blockIdx.x * 128;
    const int lda = S.lda, ldb = S.ldb;

    const __nv_bfloat16* gA0 = S.ahi + (size_t)brow*lda;
    const __nv_bfloat16* gA1 = S.alo + (size_t)brow*lda;
    const __nv_bfloat16* gB0 = S.bhi + (size_t)bcol*ldb;
    const __nv_bfloat16* gB1 = S.blo + (size_t)bcol*ldb;

    auto issue = [&](int c) {
        const uint32_t stg = smb + (uint32_t)(c % 3)*STAGE_BYTES;
        const int r = tid >> 2, q = tid & 3;
        const int r2 = r + 64;
        const size_t ka = (size_t)c*32 + q*8;
        const uint32_t o1 = SWZ(r, q), o2 = SWZ(r2, q);
        #pragma unroll
        for (int hl = 0; hl < 2; hl++) {
            const __nv_bfloat16* gA = hl ? gA1 : gA0;
            const __nv_bfloat16* gB = hl ? gB1 : gB0;
            uint32_t ba = stg + (uint32_t)hl*TILE_BYTES;
            cpasync16(ba + o1, gA + (size_t)r *lda + ka);
            cpasync16(ba + o2, gA + (size_t)r2*lda + ka);
            uint32_t bb = stg + (uint32_t)(2+hl)*TILE_BYTES;
            cpasync16(bb + o1, gB + (size_t)r *ldb + ka);
            cpasync16(bb + o2, gB + (size_t)r2*ldb + ka);
        }
    };

    float acc[2][8][4];
    #pragma unroll
    for (int mi = 0; mi < 2; mi++)
        #pragma unroll
        for (int ni = 0; ni < 8; ni++)
            #pragma unroll
            for (int q = 0; q < 4; q++) acc[mi][ni][q] = 0.f;

    const int la15 = lane & 15;
    const int qA0  = lane >> 4;                       // 0 or 1 (k-chunk within 16)
    const int brow16 = ((lane >> 4) << 3) + (lane & 7);
    const int qB0  = (lane >> 3) & 1;

    const int nC = S.K >> 5;
    issue(0); CP_COMMIT();
    if (1 < nC) issue(1);
    CP_COMMIT();

    for (int c = 0; c < nC; c++) {
        CP_WAIT1();            // chunk c landed (2 groups in flight max)
        __syncthreads();       // visible to all; all warps done reading stage (c-2)%3
        if (c + 2 < nC) issue(c + 2);
        CP_COMMIT();

        const uint32_t stb = smb + (uint32_t)(c % 3)*STAGE_BYTES;
        #pragma unroll
        for (int ks = 0; ks < 32; ks += 16) {
            const int ksq = ks >> 3;   // 0 or 2
            uint32_t ah[2][4], al[2][4];
            #pragma unroll
            for (int mi = 0; mi < 2; mi++) {
                const int row = wm*32 + mi*16 + la15;
                const uint32_t ao = SWZ(row, qA0 + ksq);
                ldsm4(ah[mi], stb + ao);
                ldsm4(al[mi], stb + TILE_BYTES + ao);
            }
            #pragma unroll
            for (int ni2 = 0; ni2 < 4; ni2++) {
                const int nrow = wn*64 + ni2*16 + brow16;
                const uint32_t bo = SWZ(nrow, qB0 + ksq);
                uint32_t bh4[4], bl4[4];
                ldsm4(bh4, stb + 2u*TILE_BYTES + bo);
                ldsm4(bl4, stb + 3u*TILE_BYTES + bo);
                #pragma unroll
                for (int half = 0; half < 2; half++) {
                    const int ni = ni2*2 + half;
                    #pragma unroll
                    for (int mi = 0; mi < 2; mi++) {
                        mma16816(acc[mi][ni], ah[mi], bh4 + half*2);
                        mma16816(acc[mi][ni], ah[mi], bl4 + half*2);
                        mma16816(acc[mi][ni], al[mi], bh4 + half*2);
                    }
                }
            }
        }
    }

    const int g2 = lane >> 2, cc = lane & 3;
    #pragma unroll
    for (int mi = 0; mi < 2; mi++) {
        #pragma unroll
        for (int ni = 0; ni < 8; ni++) {
            const int row = brow + wm*32 + mi*16;
            const int col = bcol + wn*64 + ni*8 + 2*cc;
            float b0 = 0.f, b1 = 0.f;
            if (S.bias) { b0 = S.bias[col]; b1 = S.bias[col+1]; }
            float v0 = actf(acc[mi][ni][0] + b0, S.act);
            float v1 = actf(acc[mi][ni][1] + b1, S.act);
            float v2 = actf(acc[mi][ni][2] + b0, S.act);
            float v3 = actf(acc[mi][ni][3] + b1, S.act);
            *(float2*)(S.c + (size_t)(row + g2    )*1024 + col) = make_float2(v0, v1);
            *(float2*)(S.c + (size_t)(row + g2 + 8)*1024 + col) = make_float2(v2, v3);
        }
    }
}

// ================= HMMA split-bf16 GEMM, BM=64 BN=64 (LoRA stage-1), 2-stage ======
struct LJob { const __nv_bfloat16 *ahi, *alo, *bhi, *blo; int act;
              __nv_bfloat16 *ohi, *olo; int ostride, ocol; };
struct LParams { LJob s[5]; };

#define MMA_STRIDE 40
#define L_TILE (64*MMA_STRIDE)
#define L_STAGE (4*L_TILE)
#define L_SMEM_BYTES (2*L_STAGE*2)

__global__ __launch_bounds__(128,4) void mma_lora1(LParams P)
{
    extern __shared__ __align__(16) __nv_bfloat16 sm[];
    const uint32_t smb = smem_to_u32(sm);
    LJob S = P.s[blockIdx.z];
    const int tid = threadIdx.x, lane = tid & 31, w = tid >> 5;
    const int wm = w & 1, wn = w >> 1;
    const int brow = blockIdx.y * 64;

    const __nv_bfloat16* gA0 = S.ahi + (size_t)brow*1024;
    const __nv_bfloat16* gA1 = S.alo + (size_t)brow*1024;

    auto issue = [&](int c) {
        const int st = c & 1;
        const uint32_t sbase = smb + 2u*(uint32_t)(st*L_STAGE);
        const int r = tid >> 2, q = tid & 3, r2 = r + 32;
        const size_t ka = (size_t)c*32 + q*8;
        cpasync16(sbase + 2u*(r *MMA_STRIDE + q*8),              gA0   + (size_t)r *1024 + ka);
        cpasync16(sbase + 2u*(r2*MMA_STRIDE + q*8),              gA0   + (size_t)r2*1024 + ka);
        cpasync16(sbase + 2u*(L_TILE + r *MMA_STRIDE + q*8),     gA1   + (size_t)r *1024 + ka);
        cpasync16(sbase + 2u*(L_TILE + r2*MMA_STRIDE + q*8),     gA1   + (size_t)r2*1024 + ka);
        cpasync16(sbase + 2u*(2*L_TILE + r *MMA_STRIDE + q*8),   S.bhi + (size_t)r *1024 + ka);
        cpasync16(sbase + 2u*(2*L_TILE + r2*MMA_STRIDE + q*8),   S.bhi + (size_t)r2*1024 + ka);
        cpasync16(sbase + 2u*(3*L_TILE + r *MMA_STRIDE + q*8),   S.blo + (size_t)r *1024 + ka);
        cpasync16(sbase + 2u*(3*L_TILE + r2*MMA_STRIDE + q*8),   S.blo + (size_t)r2*1024 + ka);
    };

    float acc[2][4][4];
    #pragma unroll
    for (int mi = 0; mi < 2; mi++)
        #pragma unroll
        for (int ni = 0; ni < 4; ni++)
            #pragma unroll
            for (int q = 0; q < 4; q++) acc[mi][ni][q] = 0.f;

    const int la15 = lane & 15;
    const int akc  = (lane >> 4) << 3;
    const int brow16 = ((lane >> 4) << 3) + (lane & 7);
    const int bkadd  = ((lane >> 3) & 1) << 3;

    issue(0); CP_COMMIT();
    for (int c = 0; c < 32; c++) {
        if (c + 1 < 32) { issue(c + 1); CP_COMMIT(); CP_WAIT1(); }
        else            { CP_WAIT0(); }
        __syncthreads();

        const uint32_t stb = smb + 2u*(uint32_t)((c & 1)*L_STAGE);
        #pragma unroll
        for (int ks = 0; ks < 32; ks += 16) {
            uint32_t ah[2][4], al[2][4];
            #pragma unroll
            for (int mi = 0; mi < 2; mi++) {
                const int row = wm*32 + mi*16 + la15;
                const uint32_t ao = 2u*(row*MMA_STRIDE + ks + akc);
                ldsm4(ah[mi], stb + ao);
                ldsm4(al[mi], stb + 2u*L_TILE + ao);
            }
            #pragma unroll
            for (int ni2 = 0; ni2 < 2; ni2++) {
                const int nrow = wn*32 + ni2*16 + brow16;
                const uint32_t bo = 2u*(nrow*MMA_STRIDE + ks + bkadd);
                uint32_t bh4[4], bl4[4];
                ldsm4(bh4, stb + 2u*(2*L_TILE) + bo);
                ldsm4(bl4, stb + 2u*(3*L_TILE) + bo);
                #pragma unroll
                for (int half = 0; half < 2; half++) {
                    const int ni = ni2*2 + half;
                    #pragma unroll
                    for (int mi = 0; mi < 2; mi++) {
                        mma16816(acc[mi][ni], ah[mi], bh4 + half*2);
                        mma16816(acc[mi][ni], ah[mi], bl4 + half*2);
                        mma16816(acc[mi][ni], al[mi], bh4 + half*2);
                    }
                }
            }
        }
        __syncthreads();
    }

    const int g2 = lane >> 2, cc = lane & 3;
    #pragma unroll
    for (int mi = 0; mi < 2; mi++) {
        #pragma unroll
        for (int ni = 0; ni < 4; ni++) {
            const int row = brow + wm*32 + mi*16;
            const int col = S.ocol + wn*32 + ni*8 + 2*cc;
            #pragma unroll
            for (int half = 0; half < 2; half++) {
                float v0 = actf(acc[mi][ni][half*2+0], S.act);
                float v1 = actf(acc[mi][ni][half*2+1], S.act);
                __nv_bfloat16 h0,l0,h1,l1;
                split_bf(v0,h0,l0); split_bf(v1,h1,l1);
                size_t o = (size_t)(row + g2 + half*8)*S.ostride + col;
                *(__nv_bfloat162*)(S.ohi + o) = __nv_bfloat162(h0,h1);
                *(__nv_bfloat162*)(S.olo + o) = __nv_bfloat162(l0,l1);
            }
        }
    }
}

// ---------------- post ----------------
__launch_bounds__(512)
__global__ void post_kernel(float* __restrict__ K_, float* __restrict__ V_,
    float* __restrict__ WL, const float* __restrict__ A_, const float* __restrict__ R_,
    const float* __restrict__ HV, const float* __restrict__ vfirst,
    const float* __restrict__ kkv, const float* __restrict__ kav, const float* __restrict__ rkv,
    float* __restrict__ AT, float* __restrict__ BTt, float* __restrict__ RKS)
{
    int bt = blockIdx.x;
    int h = threadIdx.x >> 5, lane = threadIdx.x & 31;
    int base = bt * D_ + h * HS_;
    int ce0 = h*HS_ + lane, ce1 = ce0 + 32;
    int i0 = base + lane, i1 = i0 + 32;

    float k0 = K_[i0], k1 = K_[i1];
    float kk0 = k0 * kkv[ce0], kk1 = k1 * kkv[ce1];
    float n2 = kk0*kk0 + kk1*kk1;
    #pragma unroll
    for (int o = 16; o; o >>= 1) n2 += __shfl_xor_sync(0xffffffffu, n2, o);
    float inv = rsqrtf(n2);
    kk0 *= inv; kk1 *= inv;

    float a0 = A_[i0], a1 = A_[i1];
    AT[i0] = -kk0;      AT[i1] = -kk1;
    BTt[i0] = kk0 * a0; BTt[i1] = kk1 * a1;

    k0 *= 1.f + (a0 - 1.f) * kav[ce0];
    k1 *= 1.f + (a1 - 1.f) * kav[ce1];
    K_[i0] = k0; K_[i1] = k1;

    float v0 = V_[i0], v1 = V_[i1];
    float hg0 = HV[i0], hg1 = HV[i1];
    v0 += (vfirst[i0] - v0) * hg0;
    v1 += (vfirst[i1] - v1) * hg1;
    V_[i0] = v0; V_[i1] = v1;

    float w0 = WL[i0], w1 = WL[i1];
    WL[i0] = expf(DECAY_C / (1.f + expf(-w0)));
    WL[i1] = expf(DECAY_C / (1.f + expf(-w1)));

    float rs = R_[i0]*k0*rkv[ce0] + R_[i1]*k1*rkv[ce1];
    #pragma unroll
    for (int o = 16; o; o >>= 1) rs += __shfl_xor_sync(0xffffffffu, rs, o);
    if (lane == 0) RKS[bt*H_ + h] = rs;
}

// ---------------- scan: cp.async 8-slot ring (6 steps of slack), 1 barrier/step ---
#define LOAD8(dst, ptr) do { \
    float4 u0 = *(const float4*)(ptr); float4 u1 = *(const float4*)((ptr)+4); \
    dst[0]=u0.x; dst[1]=u0.y; dst[2]=u0.z; dst[3]=u0.w; \
    dst[4]=u1.x; dst[5]=u1.y; dst[6]=u1.z; dst[7]=u1.w; } while(0)

__launch_bounds__(256)
__global__ void scan_kernel(const float* __restrict__ R_, const float* __restrict__ W_,
    const float* __restrict__ K_, const float* __restrict__ V_,
    const float* __restrict__ AT, const float* __restrict__ BTt,
    float* __restrict__ Y, float* __restrict__ S)
{
    __shared__ __align__(16) float4 vbuf[8][88];
    __shared__ float redA[2][8][32];
    __shared__ float redY[2][8][32];
    int bid = blockIdx.x;
    int b = bid >> 5; int rem = bid & 31; int h = rem >> 1; int half = rem & 1;
    int tid = threadIdx.x;
    int kg = tid >> 5, vl = tid & 31;
    int kb = kg * 8;

    const float* msrc = nullptr;
    if (tid < 88) {
        const float* bp; int inner;
        if (tid < 80) {
            int arr = tid / 16, q = tid % 16;
            bp = (arr==0) ? AT : (arr==1) ? W_ : (arr==2) ? BTt : (arr==3) ? K_ : R_;
            inner = q * 4;
        } else {
            bp = V_; inner = half*32 + (tid - 80) * 4;
        }
        msrc = bp + h*HS_ + inner;
    }

    const uint32_t vbase = smem_to_u32(vbuf);
    const uint32_t vslot = (uint32_t)tid * 16u;

    float s[8];
    #pragma unroll
    for (int i = 0; i < 8; i++) s[i] = 0.f;
    float yprev = 0.f;

    size_t row0 = (size_t)b * T_ * D_;
    const size_t yofs = row0 + h*HS_ + half*32 + vl;

    #pragma unroll
    for (int i = 0; i < 7; i++) {
        if (tid < 88) cpasync16(vbase + (uint32_t)i*(88*16) + vslot, msrc + row0 + (size_t)i*D_);
        CP_COMMIT();
    }
    CP_WAIT6();
    __syncthreads();

    for (int t = 0; t < T_; t++) {
        const int cb = t & 1;
        if (tid < 88 && t + 7 < T_)
            cpasync16(vbase + (uint32_t)((t+7)&7)*(88*16) + vslot, msrc + row0 + (size_t)(t+7)*D_);
        CP_COMMIT();
        CP_WAIT6();

        const float* base = (const float*)vbuf[t & 7];
        float atr[8], wr[8], btr[8], kr[8], rr[8];
        LOAD8(atr, base       + kb); LOAD8(wr, base +  64 + kb); LOAD8(btr, base + 128 + kb);
        LOAD8(kr,  base + 192 + kb); LOAD8(rr, base + 256 + kb);
        float vt = base[320 + vl];

        float p0 = s[0]*atr[0] + s[1]*atr[1], p1 = s[2]*atr[2] + s[3]*atr[3];
        float p2 = s[4]*atr[4] + s[5]*atr[5], p3 = s[6]*atr[6] + s[7]*atr[7];
        redA[cb][kg][vl] = (p0 + p1) + (p2 + p3);
        redY[cb][kg][vl] = yprev;
        __syncthreads();

        float sa = 0.f;
        #pragma unroll
        for (int g2 = 0; g2 < 8; g2++) sa += redA[cb][g2][vl];

        if (kg == 0 && t > 0) {
            float yy = 0.f;
            #pragma unroll
            for (int g2 = 0; g2 < 8; g2++) yy += redY[cb][g2][vl];
            Y[yofs + (size_t)(t-1)*D_] = yy;
        }

        float y = 0.f;
        #pragma unroll
        for (int i = 0; i < 8; i++) {
            float sn = s[i]*wr[i] + sa*btr[i] + vt*kr[i];
            s[i] = sn;
            y += sn * rr[i];
        }
        yprev = y;
    }
    redY[0][kg][vl] = yprev;
    __syncthreads();
    if (kg == 0) {
        float yy = 0.f;
        #pragma unroll
        for (int g2 = 0; g2 < 8; g2++) yy += redY[0][g2][vl];
        Y[yofs + (size_t)(T_-1)*D_] = yy;
    }

    int v = half*32 + vl;
    size_t sb2 = ((size_t)(b*H_ + h)*HS_ + v)*HS_ + kb;
    *(float4*)(S + sb2)     = make_float4(s[0], s[1], s[2], s[3]);
    *(float4*)(S + sb2 + 4) = make_float4(s[4], s[5], s[6], s[7]);
}

// ---------------- groupnorm + residual + gate + bf16 split ----------------
__launch_bounds__(512)
__global__ void gn_kernel(const float* __restrict__ Y, const float* __restrict__ V_,
    const float* __restrict__ G_, const float* __restrict__ RKS,
    const float* __restrict__ gsc, const float* __restrict__ gbi)
{
    int bt = blockIdx.x;
    int h = threadIdx.x >> 5, lane = threadIdx.x & 31;
    int base = bt * D_ + h * HS_;
    int i0 = base + lane, i1 = i0 + 32;
    int ce0 = h*HS_ + lane, ce1 = ce0 + 32;
    float y0 = Y[i0], y1 = Y[i1];
    float sm = y0 + y1, sq = y0*y0 + y1*y1;
    #pragma unroll
    for (int o = 16; o; o >>= 1) {
        sm += __shfl_xor_sync(0xffffffffu, sm, o);
        sq += __shfl_xor_sync(0xffffffffu, sq, o);
    }
    float mu  = sm * (1.f/64.f);
    float var = sq * (1.f/64.f) - mu*mu;
    float inv = rsqrtf(var + 1e-5f);
    float rk  = RKS[bt*H_ + h];
    float o0 = ((y0 - mu)*inv*gsc[ce0] + gbi[ce0] + rk*V_[i0]) * G_[i0];
    float o1 = ((y1 - mu)*inv*gsc[ce1] + gbi[ce1] + rk*V_[i1]) * G_[i1];
    __nv_bfloat16 h0,l0,h1,l1;
    split_bf(o0, h0, l0); split_bf(o1, h1, l1);
    g_zhi[i0] = h0; g_zhi[i1] = h1;
    g_zlo[i0] = l0; g_zlo[i1] = l1;
}

// ---------------- launch ----------------
extern "C" void kernel_launch(void* const* d_in, const int* in_sizes, int n_in,
                              void* d_out, int out_size)
{
    const float* cur    = (const float*)d_in[0];
    const float* prev   = (const float*)d_in[1];
    const float* vfirst = (const float*)d_in[2];
    const float* lam    = (const float*)d_in[3];
    const float* rw_W   = (const float*)d_in[4];
    const float* w1     = (const float*)d_in[5];
    const float* w2     = (const float*)d_in[6];
    const float* w2b    = (const float*)d_in[7];
    const float* kw     = (const float*)d_in[8];
    const float* vw     = (const float*)d_in[9];
    const float* a1     = (const float*)d_in[10];
    const float* a2     = (const float*)d_in[11];
    const float* a2b    = (const float*)d_in[12];
    const float* v1     = (const float*)d_in[13];
    const float* v2     = (const float*)d_in[14];
    const float* v2b    = (const float*)d_in[15];
    const float* g1     = (const float*)d_in[16];
    const float* g2     = (const float*)d_in[17];
    const float* g2b    = (const float*)d_in[18];
    const float* k_k    = (const float*)d_in[19];
    const float* k_a    = (const float*)d_in[20];
    const float* r_k    = (const float*)d_in[21];
    const float* gsc    = (const float*)d_in[22];
    const float* gbi    = (const float*)d_in[23];
    const float* outW   = (const float*)d_in[24];
    (void)in_sizes; (void)n_in;

    float *pr,*pwl,*pk,*pv,*pa,*pg,*pat,*pbt,*phv,*prks,*py,*pds;
    cudaGetSymbolAddress((void**)&pr,  g_r);
    cudaGetSymbolAddress((void**)&pwl, g_wl);
    cudaGetSymbolAddress((void**)&pk,  g_k);
    cudaGetSymbolAddress((void**)&pv,  g_v);
    cudaGetSymbolAddress((void**)&pa,  g_a);
    cudaGetSymbolAddress((void**)&pg,  g_g);
    cudaGetSymbolAddress((void**)&pat, g_at);
    cudaGetSymbolAddress((void**)&pbt, g_bt);
    cudaGetSymbolAddress((void**)&phv, g_hv);
    cudaGetSymbolAddress((void**)&prks,g_rks);
    cudaGetSymbolAddress((void**)&py,  g_y);
    cudaGetSymbolAddress((void**)&pds, g_ds);

    __nv_bfloat16 *pwhiT,*pwloT,*pahi,*palo,*pzhi,*pzlo,*pl1h,*pl1l,*pl2h,*pl2l,*ps1h,*ps1l;
    cudaGetSymbolAddress((void**)&pwhiT, g_whiT);
    cudaGetSymbolAddress((void**)&pwloT, g_wloT);
    cudaGetSymbolAddress((void**)&pahi,  g_ahi);
    cudaGetSymbolAddress((void**)&palo,  g_alo);
    cudaGetSymbolAddress((void**)&pzhi,  g_zhi);
    cudaGetSymbolAddress((void**)&pzlo,  g_zlo);
    cudaGetSymbolAddress((void**)&pl1h,  g_l1hi);
    cudaGetSymbolAddress((void**)&pl1l,  g_l1lo);
    cudaGetSymbolAddress((void**)&pl2h,  g_l2hi);
    cudaGetSymbolAddress((void**)&pl2l,  g_l2lo);
    cudaGetSymbolAddress((void**)&ps1h,  g_s1hi);
    cudaGetSymbolAddress((void**)&ps1l,  g_s1lo);

    float* out = (float*)d_out;
    const int YN = BT_*D_;
    const int SN = B_*H_*HS_*HS_;
    float* stateOut = (out_size >= YN + SN) ? (out + YN) : pds;

    cudaFuncSetAttribute(mma_gemm,  cudaFuncAttributeMaxDynamicSharedMemorySize, MMA_SMEM_BYTES);
    cudaFuncSetAttribute(mma_lora1, cudaFuncAttributeMaxDynamicSharedMemorySize, L_SMEM_BYTES);

    const size_t O_W1 = 0, O_A1 = 64*1024, O_V1 = 128*1024, O_G1 = 192*1024;
    const size_t P_W2 = 0, P_A2 = 1024*64, P_V2 = 2*1024*64, P_G2 = 3*1024*64;
    const size_t S_HW = 0, S_HA = (size_t)BT_*64, S_HV = (size_t)BT_*128, S_HG = (size_t)BT_*192;

    dummy_kernel<<<1, 32>>>();

    TSParams TP;
    TP.j[0]  = { rw_W, 1024, 1024, pwhiT + 0*1024*1024, pwloT + 0*1024*1024, 1024 };
    TP.j[1]  = { kw,   1024, 1024, pwhiT + 1*1024*1024, pwloT + 1*1024*1024, 1024 };
    TP.j[2]  = { vw,   1024, 1024, pwhiT + 2*1024*1024, pwloT + 2*1024*1024, 1024 };
    TP.j[3]  = { outW, 1024, 1024, pwhiT + 3*1024*1024, pwloT + 3*1024*1024, 1024 };
    TP.j[4]  = { w1, 1024,  64, pl1h + O_W1, pl1l + O_W1, 1024 };
    TP.j[5]  = { a1, 1024,  64, pl1h + O_A1, pl1l + O_A1, 1024 };
    TP.j[6]  = { v1, 1024,  32, pl1h + O_V1, pl1l + O_V1, 1024 };
    TP.j[7]  = { g1, 1024, 128, pl1h + O_G1, pl1l + O_G1, 1024 };
    TP.j[8]  = { w2,  64, 1024, pl2h + P_W2, pl2l + P_W2,  64 };
    TP.j[9]  = { a2,  64, 1024, pl2h + P_A2, pl2l + P_A2,  64 };
    TP.j[10] = { v2,  32, 1024, pl2h + P_V2, pl2l + P_V2,  64 };
    TP.j[11] = { g2, 128, 1024, pl2h + P_G2, pl2l + P_G2, 128 };
    tsplit_kernel<<<dim3(32,32,12), 256>>>(TP);
    asplit_kernel<<<4096, 256>>>(cur, prev, lam);

    MParams Prkv;
    {
        const int br[3] = {0, 2, 3};
        float* cs[3] = {pr, pk, pv};
        for (int z = 0; z < 3; z++) {
            Prkv.s[z] = { pahi + (size_t)br[z]*BT_*D_, palo + (size_t)br[z]*BT_*D_,
                          pwhiT + (size_t)z*1024*1024, pwloT + (size_t)z*1024*1024,
                          1024, 1024, 1024, nullptr, 0, cs[z] };
        }
        Prkv.s[3] = Prkv.s[0];
    }
    mma_gemm<<<dim3(8,32,3), 256, MMA_SMEM_BYTES>>>(Prkv);

    LParams LP;
    LP.s[0] = { pahi + (size_t)1*BT_*D_, palo + (size_t)1*BT_*D_, pl1h+O_W1, pl1l+O_W1, 1, ps1h+S_HW, ps1l+S_HW,  64, 0 };
    LP.s[1] = { pahi + (size_t)4*BT_*D_, palo + (size_t)4*BT_*D_, pl1h+O_A1, pl1l+O_A1, 0, ps1h+S_HA, ps1l+S_HA,  64, 0 };
    LP.s[2] = { pahi + (size_t)3*BT_*D_, palo + (size_t)3*BT_*D_, pl1h+O_V1, pl1l+O_V1, 0, ps1h+S_HV, ps1l+S_HV,  64, 0 };
    LP.s[3] = { pahi + (size_t)5*BT_*D_, palo + (size_t)5*BT_*D_, pl1h+O_G1,         pl1l+O_G1,         2, ps1h+S_HG, ps1l+S_HG, 128, 0 };
    LP.s[4] = { pahi + (size_t)5*BT_*D_, palo + (size_t)5*BT_*D_, pl1h+O_G1+64*1024, pl1l+O_G1+64*1024, 2, ps1h+S_HG, ps1l+S_HG, 128, 64 };
    mma_lora1<<<dim3(1,64,5), 128, L_SMEM_BYTES>>>(LP);

    MParams P2;
    P2.s[0] = { ps1h+S_HW, ps1l+S_HW, pl2h+P_W2, pl2l+P_W2,  64,  64,  64, w2b, 0, pwl };
    P2.s[1] = { ps1h+S_HA, ps1l+S_HA, pl2h+P_A2, pl2l+P_A2,  64,  64,  64, a2b, 2, pa  };
    P2.s[2] = { ps1h+S_HV, ps1l+S_HV, pl2h+P_V2, pl2l+P_V2,  64,  64,  64, v2b, 2, phv };
    P2.s[3] = { ps1h+S_HG, ps1l+S_HG, pl2h+P_G2, pl2l+P_G2, 128, 128, 128, g2b, 0, pg  };
    mma_gemm<<<dim3(8,32,4), 256, MMA_SMEM_BYTES>>>(P2);

    post_kernel<<<BT_, 512>>>(pk, pv, pwl, pa, pr, phv, vfirst, k_k, k_a, r_k, pat, pbt, prks);
    scan_kernel<<<128, 256>>>(pr, pwl, pk, pv, pat, pbt, py, stateOut);
    gn_kernel  <<<BT_, 512>>>(py, pv, pg, prks, gsc, gbi);

    MParams Pout;
    Pout.s[0] = { pzhi, pzlo, pwhiT + (size_t)3*1024*1024, pwloT + (size_t)3*1024*1024,
                  1024, 1024, 1024, nullptr, 0, out };
    Pout.s[1] = Pout.s[0]; Pout.s[2] = Pout.s[0]; Pout.s[3] = Pout.s[0];
    mma_gemm<<<dim3(8,32,1), 256, MMA_SMEM_BYTES>>>(Pout);

    if (out_size >= YN + SN + YN)
        cudaMemcpyAsync(out + YN + SN, vfirst, (size_t)YN*sizeof(float),
                        cudaMemcpyDeviceToDevice, 0);
}